// round 15
// baseline (speedup 1.0000x reference)
#include <cuda_runtime.h>
#include <cuda_fp16.h>
#include <math.h>
#include <stdint.h>

#define BATCH 2
#define SEQ   2048
#define DIM   1024
#define HEADS 16
#define HDIM  64
#define TOKENS (BATCH*SEQ)        /* 4096 */
#define NCLUST 64                 /* B*C = 2*32 */
#define DD ((size_t)DIM*DIM)

// ---------------- scratch (static device arrays; no allocations) ----------------
__device__ float g_h1 [(size_t)TOKENS*DIM];
__device__ float g_h2 [(size_t)TOKENS*DIM];

__device__ float s_reps [NCLUST*DIM];
__device__ float s_mlpin[NCLUST*DIM];
__device__ float s_t1   [NCLUST*DIM];
__device__ float s_mix  [NCLUST*DIM];
__device__ float s_rqkv [NCLUST*3*DIM];
__device__ float s_ratt [NCLUST*DIM];
__device__ float s_rnew [NCLUST*DIM];
__device__ float s_gproj[NCLUST*DIM];

__device__ float w_gqkv[3*DD];
__device__ float b_gqkv[3*DIM];
__device__ float b_qkv [2*3*DIM];

// fp16 buffers
__device__ __half w_qkv[6*DD];
__device__ __half w_lo[2*DD];
__device__ __half w_g1[2*DD];
__device__ __half w_g2[DD];
__device__ __half a_x   [(size_t)TOKENS*DIM];
__device__ __half a_qkv [(size_t)TOKENS*3*DIM];
__device__ __half a_att [(size_t)TOKENS*DIM];
__device__ __half a_h1  [(size_t)TOKENS*DIM];
__device__ __half a_h2  [(size_t)TOKENS*DIM];
__device__ __half a_hid [(size_t)TOKENS*DIM];

// ---------------- PTX helpers ----------------
__device__ __forceinline__ uint32_t smem_u32(const void* p) {
    uint32_t a;
    asm("{ .reg .u64 t; cvta.to.shared.u64 t, %1; cvt.u32.u64 %0, t; }" : "=r"(a) : "l"(p));
    return a;
}
__device__ __forceinline__ void cpa16(uint32_t saddr, const void* g) {
    asm volatile("cp.async.cg.shared.global [%0], [%1], 16;" :: "r"(saddr), "l"(g));
}
#define CP_COMMIT() asm volatile("cp.async.commit_group;" ::: "memory")
template<int N>
__device__ __forceinline__ void cp_wait() {
    asm volatile("cp.async.wait_group %0;" :: "n"(N) : "memory");
}
__device__ __forceinline__ uint32_t cvt_tf32(float v) {
    uint32_t r;
    asm("cvt.rna.tf32.f32 %0, %1;" : "=r"(r) : "f"(v));
    return r;
}
__device__ __forceinline__ void mma8(float* c, const uint32_t* a, const uint32_t* b) {
    asm volatile(
        "mma.sync.aligned.m16n8k8.row.col.f32.tf32.tf32.f32 "
        "{%0,%1,%2,%3}, {%4,%5,%6,%7}, {%8,%9}, {%0,%1,%2,%3};"
        : "+f"(c[0]), "+f"(c[1]), "+f"(c[2]), "+f"(c[3])
        : "r"(a[0]), "r"(a[1]), "r"(a[2]), "r"(a[3]), "r"(b[0]), "r"(b[1]));
}
__device__ __forceinline__ void mma16h(float* c, const uint32_t* a, const uint32_t* b) {
    asm volatile(
        "mma.sync.aligned.m16n8k16.row.col.f32.f16.f16.f32 "
        "{%0,%1,%2,%3}, {%4,%5,%6,%7}, {%8,%9}, {%0,%1,%2,%3};"
        : "+f"(c[0]), "+f"(c[1]), "+f"(c[2]), "+f"(c[3])
        : "r"(a[0]), "r"(a[1]), "r"(a[2]), "r"(a[3]), "r"(b[0]), "r"(b[1]));
}
__device__ __forceinline__ void ldsm4(uint32_t* r, uint32_t saddr) {
    asm volatile("ldmatrix.sync.aligned.m8n8.x4.shared.b16 {%0,%1,%2,%3}, [%4];"
        : "=r"(r[0]), "=r"(r[1]), "=r"(r[2]), "=r"(r[3]) : "r"(saddr));
}
__device__ __forceinline__ void ldsm4t(uint32_t* r, uint32_t saddr) {
    asm volatile("ldmatrix.sync.aligned.m8n8.x4.trans.shared.b16 {%0,%1,%2,%3}, [%4];"
        : "=r"(r[0]), "=r"(r[1]), "=r"(r[2]), "=r"(r[3]) : "r"(saddr));
}
__device__ __forceinline__ uint32_t packh2(float a, float b) {
    __half2 h = __floats2half2_rn(a, b);
    return *(uint32_t*)&h;
}

// ---------------- epilogue (act: 0 none, 1 gelu, 2 sigmoid) ----------------
__device__ __forceinline__ float epilogue(float v, int m, int n,
                                          const float* __restrict__ bias,
                                          const float* __restrict__ add, int addDiv,
                                          int addLd, int act) {
    if (bias) v += bias[n];
    if (add)  v += add[(size_t)(m / addDiv) * addLd + n];
    if (act == 1) {
        v = 0.5f * v * (1.0f + erff(v * 0.70710678118654752f));
    } else if (act == 2) {
        v = 1.0f / (1.0f + expf(-v));
    }
    return v;
}

// ---------------- fp32 -> fp16 bulk conversion (single launch, 10 segments) ----------------
struct CvtArgs {
    const float* src[10];
    __half* dst[10];
    int n[10];
};
__global__ void f2h_kernel(CvtArgs args) {
    const int seg = blockIdx.y;
    const int n4 = args.n[seg] >> 2;
    const float4* s = (const float4*)args.src[seg];
    __half2* d = (__half2*)args.dst[seg];
    for (int i = blockIdx.x * blockDim.x + threadIdx.x; i < n4; i += gridDim.x * blockDim.x) {
        float4 v = s[i];
        d[2*i]   = __floats2half2_rn(v.x, v.y);
        d[2*i+1] = __floats2half2_rn(v.z, v.w);
    }
}

// ---------------- fp32 pack copies (single launch, 12 segments) ----------------
struct PackArgs {
    const float* src[12];
    float* dst[12];
    int n[12];
};
__global__ void packf_kernel(PackArgs args) {
    const int seg = blockIdx.y;
    const int n4 = args.n[seg] >> 2;
    const float4* s = (const float4*)args.src[seg];
    float4* d = (float4*)args.dst[seg];
    for (int i = blockIdx.x * blockDim.x + threadIdx.x; i < n4; i += gridDim.x * blockDim.x)
        d[i] = s[i];
}

// ---------------- fp16 mma GEMM: C[M,N] = A[M,K] * B[N,K]^T (+bias,+add,act) ----------------
// 128x128 CTA tile, 8 warps (2x4), warp tile 64x32, BK=32, 4-stage cp.async. (R9/R11 proven)
// MERGE=true: final-gate variant — C = XL + sigmoid(v+bias) * (add_bcast - XL).
#define HPITCH 40
#define HSTAGES 4
#define GEMM_H_SMEM (HSTAGES * 2 * 128 * HPITCH * 2)   /* 81920 */

template<bool MERGE>
__global__ __launch_bounds__(256, 2)
void gemm_h(const __half* __restrict__ A,
            const __half* __restrict__ B, int ldb,
            const float* __restrict__ bias,
            const float* __restrict__ add, int addDiv, int addLd,
            float* __restrict__ C, __half* __restrict__ Ch,
            int M, int Nn, int K, int act,
            const float* __restrict__ XL)
{
    extern __shared__ __half hsm[];
    __half* Asm = hsm;
    __half* Bsm = hsm + HSTAGES * 128 * HPITCH;

    const int tid  = threadIdx.x;
    const int wid  = tid >> 5;
    const int lane = tid & 31;
    const int warp_m = wid >> 2;     // 0..1
    const int warp_n = wid & 3;      // 0..3
    const int m0 = blockIdx.y * 128;
    const int n0 = blockIdx.x * 128;
    const int g = lane >> 2;
    const int t = lane & 3;

    const uint32_t a_loff = ((uint32_t)(lane & 15) * HPITCH + (uint32_t)(lane >> 4) * 8) * 2;
    const uint32_t b_row  = (uint32_t)(lane & 7) + (uint32_t)((lane >> 1) & 8);
    const uint32_t b_loff = (b_row * HPITCH + (uint32_t)(lane & 8)) * 2;

    float acc[4][4][4];
#pragma unroll
    for (int mi = 0; mi < 4; ++mi)
#pragma unroll
        for (int ni = 0; ni < 4; ++ni)
#pragma unroll
            for (int r = 0; r < 4; ++r) acc[mi][ni][r] = 0.f;

    auto load = [&](int kc, int s) {
        const int k0 = kc * 32;
        __half* da = Asm + s * 128 * HPITCH;
        __half* db = Bsm + s * 128 * HPITCH;
#pragma unroll
        for (int f = tid; f < 512; f += 256) {
            int r = f >> 2, c = f & 3;
            int am = m0 + r; if (am > M - 1) am = M - 1;
            cpa16(smem_u32(da + r * HPITCH + c * 8), A + (size_t)am * K + k0 + c * 8);
        }
#pragma unroll
        for (int f = tid; f < 512; f += 256) {
            int r = f >> 2, c = f & 3;
            cpa16(smem_u32(db + r * HPITCH + c * 8), B + (size_t)(n0 + r) * ldb + k0 + c * 8);
        }
    };

    auto compute = [&](int s) {
        const uint32_t abase = smem_u32(Asm + s * 128 * HPITCH + warp_m * 64 * HPITCH) + a_loff;
        const uint32_t bbase = smem_u32(Bsm + s * 128 * HPITCH + warp_n * 32 * HPITCH) + b_loff;
#pragma unroll
        for (int ks = 0; ks < 2; ++ks) {
            uint32_t af[4][4], bf[4][2];
#pragma unroll
            for (int mi = 0; mi < 4; ++mi)
                ldsm4(af[mi], abase + (uint32_t)(mi * 16 * HPITCH + ks * 16) * 2);
#pragma unroll
            for (int p = 0; p < 2; ++p) {
                uint32_t r[4];
                ldsm4(r, bbase + (uint32_t)(p * 16 * HPITCH + ks * 16) * 2);
                bf[2*p][0] = r[0]; bf[2*p][1] = r[1];
                bf[2*p+1][0] = r[2]; bf[2*p+1][1] = r[3];
            }
#pragma unroll
            for (int mi = 0; mi < 4; ++mi)
#pragma unroll
                for (int ni = 0; ni < 4; ++ni)
                    mma16h(acc[mi][ni], af[mi], bf[ni]);
        }
    };

    const int NC = K >> 5;
#pragma unroll
    for (int s = 0; s < HSTAGES - 1; ++s) {
        if (s < NC) load(s, s);
        CP_COMMIT();
    }
    for (int kc = 0; kc < NC; ++kc) {
        if (kc + HSTAGES - 1 < NC) {
            load(kc + HSTAGES - 1, (kc + HSTAGES - 1) & (HSTAGES - 1));
            CP_COMMIT();
            cp_wait<HSTAGES - 1>();
        } else {
            cp_wait<0>();
        }
        __syncthreads();
        compute(kc & (HSTAGES - 1));
        __syncthreads();
    }

#pragma unroll
    for (int mi = 0; mi < 4; ++mi) {
#pragma unroll
        for (int ni = 0; ni < 4; ++ni) {
            int row = m0 + warp_m * 64 + mi * 16 + g;
            int col = n0 + warp_n * 32 + ni * 8 + 2 * t;
#pragma unroll
            for (int half_ = 0; half_ < 2; ++half_) {
                int rr = row + half_ * 8;
                if (rr >= M) continue;
                if (MERGE) {
                    float2 o;
#pragma unroll
                    for (int e = 0; e < 2; ++e) {
                        float v = acc[mi][ni][half_*2 + e] + bias[col + e];
                        float sx = 1.f / (1.f + expf(-v));
                        float xl = XL[(size_t)rr * Nn + col + e];
                        float xg = add[(size_t)(rr / addDiv) * addLd + col + e];
                        ((float*)&o)[e] = xl + sx * (xg - xl);
                    }
                    *(float2*)&C[(size_t)rr * Nn + col] = o;
                } else {
                    float vx = epilogue(acc[mi][ni][half_*2],   rr, col,     bias, add, addDiv, addLd, act);
                    float vy = epilogue(acc[mi][ni][half_*2+1], rr, col + 1, bias, add, addDiv, addLd, act);
                    if (C)  *(float2*)&C[(size_t)rr * Nn + col] = make_float2(vx, vy);
                    if (Ch) *(__half2*)&Ch[(size_t)rr * Nn + col] = __floats2half2_rn(vx, vy);
                }
            }
        }
    }
}

// ---------------- tf32 mma.sync GEMM (small cluster chain), BK=64, 2 stages (R11 proven) ----------------
#define SPITCH 68

template<int BM, int BN, int WM, int WN, int NSTAGE>
__global__ __launch_bounds__(256, 3)
void gemm_mma(const float* __restrict__ A,
              const float* __restrict__ B, int ldb,
              const float* __restrict__ bias,
              const float* __restrict__ add, int addDiv,
              float* __restrict__ C, int M, int Nn, int K, int act)
{
    constexpr int MI  = WM / 16;
    constexpr int NI  = WN / 8;
    constexpr int WGN = BN / WN;

    extern __shared__ float sm[];
    float* Asm = sm;
    float* Bsm = sm + NSTAGE * BM * SPITCH;

    const int tid  = threadIdx.x;
    const int wid  = tid >> 5;
    const int lane = tid & 31;
    const int warp_m = wid / WGN;
    const int warp_n = wid % WGN;
    const int m0 = blockIdx.y * BM;
    const int n0 = blockIdx.x * BN;
    const int g = lane >> 2;
    const int t = lane & 3;

    float acc[MI][NI][4];
#pragma unroll
    for (int mi = 0; mi < MI; ++mi)
#pragma unroll
        for (int ni = 0; ni < NI; ++ni)
#pragma unroll
            for (int r = 0; r < 4; ++r) acc[mi][ni][r] = 0.f;

    auto load = [&](int kc, int s) {
        const int k0 = kc * 64;
        float* da = Asm + s * BM * SPITCH;
        float* db = Bsm + s * BN * SPITCH;
#pragma unroll
        for (int f = tid; f < BM * 16; f += 256) {
            int r = f >> 4, c4 = f & 15;
            int am = m0 + r; if (am > M - 1) am = M - 1;
            cpa16(smem_u32(da + r * SPITCH + c4 * 4), A + (size_t)am * K + k0 + c4 * 4);
        }
#pragma unroll
        for (int f = tid; f < BN * 16; f += 256) {
            int r = f >> 4, c4 = f & 15;
            cpa16(smem_u32(db + r * SPITCH + c4 * 4), B + (size_t)(n0 + r) * ldb + k0 + c4 * 4);
        }
    };

    auto compute = [&](int s) {
        const float* da = Asm + s * BM * SPITCH + (size_t)warp_m * WM * SPITCH;
        const float* db = Bsm + s * BN * SPITCH + (size_t)warp_n * WN * SPITCH;
#pragma unroll
        for (int ks = 0; ks < 8; ++ks) {
            uint32_t af[MI][4], bf[NI][2];
#pragma unroll
            for (int mi = 0; mi < MI; ++mi) {
                const float* p = da + (mi * 16 + g) * SPITCH + ks * 8 + t;
                af[mi][0] = cvt_tf32(p[0]);
                af[mi][1] = cvt_tf32(p[8 * SPITCH]);
                af[mi][2] = cvt_tf32(p[4]);
                af[mi][3] = cvt_tf32(p[8 * SPITCH + 4]);
            }
#pragma unroll
            for (int ni = 0; ni < NI; ++ni) {
                const float* p = db + (ni * 8 + g) * SPITCH + ks * 8 + t;
                bf[ni][0] = cvt_tf32(p[0]);
                bf[ni][1] = cvt_tf32(p[4]);
            }
#pragma unroll
            for (int mi = 0; mi < MI; ++mi)
#pragma unroll
                for (int ni = 0; ni < NI; ++ni)
                    mma8(acc[mi][ni], af[mi], bf[ni]);
        }
    };

    const int NC = K >> 6;
#pragma unroll
    for (int s = 0; s < NSTAGE - 1; ++s) {
        if (s < NC) load(s, s);
        CP_COMMIT();
    }
    for (int kc = 0; kc < NC; ++kc) {
        if (kc + NSTAGE - 1 < NC) {
            load(kc + NSTAGE - 1, (kc + NSTAGE - 1) % NSTAGE);
            CP_COMMIT();
            cp_wait<NSTAGE - 1>();
        } else {
            cp_wait<0>();
        }
        __syncthreads();
        compute(kc % NSTAGE);
        __syncthreads();
    }

#pragma unroll
    for (int mi = 0; mi < MI; ++mi) {
#pragma unroll
        for (int ni = 0; ni < NI; ++ni) {
            int row = m0 + warp_m * WM + mi * 16 + g;
            int col = n0 + warp_n * WN + ni * 8 + 2 * t;
            if (row < M) {
                float2 v0;
                v0.x = epilogue(acc[mi][ni][0], row, col,     bias, add, addDiv, Nn, act);
                v0.y = epilogue(acc[mi][ni][1], row, col + 1, bias, add, addDiv, Nn, act);
                *(float2*)&C[(size_t)row * Nn + col] = v0;
            }
            if (row + 8 < M) {
                float2 v1;
                v1.x = epilogue(acc[mi][ni][2], row + 8, col,     bias, add, addDiv, Nn, act);
                v1.y = epilogue(acc[mi][ni][3], row + 8, col + 1, bias, add, addDiv, Nn, act);
                *(float2*)&C[(size_t)(row + 8) * Nn + col] = v1;
            }
        }
    }
}

#define GEMM_SMEM_SM  (2*(64+64)*SPITCH*4)    /* 69632 */

// ---------------- flash attention (windowed causal), full fp16 mma ----------------
// 128 queries/block, 8 warps (256 threads), 64-key K/V chunks double-buffered.
#define FPITCH 72

__global__ __launch_bounds__(256, 2)
void flash_attn_h(const __half* __restrict__ QKV, int ldq, __half* __restrict__ Oh)
{
    const int i0 = blockIdx.x * 128;
    const int h = blockIdx.y, b = blockIdx.z;
    const size_t hb = (size_t)b * SEQ * ldq + (size_t)h * HDIM;
    const size_t ho = (size_t)b * SEQ * DIM + (size_t)h * HDIM;
    const __half* Q = QKV + hb;
    const __half* K = QKV + hb + DIM;
    const __half* V = QKV + hb + 2 * DIM;
    const int tid = threadIdx.x;
    const int wid = tid >> 5;     // 0..7 -> query rows wid*16..wid*16+15
    const int lane = tid & 31;
    const int g = lane >> 2;
    const int t = lane & 3;

    __shared__ __align__(16) __half Ks[2][64 * FPITCH];
    __shared__ __align__(16) __half Vs[2][64 * FPITCH];

    // ---- stage Q tile (128 rows: 0-63 in Ks[0], 64-127 in Vs[0]), build fragments ----
    for (int e = tid; e < 1024; e += 256) {
        int r = e >> 3, c8 = (e & 7) * 8;
        float4 qv = *(const float4*)(Q + (size_t)(i0 + r) * ldq + c8);
        if (r < 64) *(float4*)&Ks[0][r * FPITCH + c8] = qv;
        else        *(float4*)&Vs[0][(r - 64) * FPITCH + c8] = qv;
    }
    __syncthreads();
    uint32_t qf[4][4];
    {
        const __half* qbuf = (wid < 4) ? Ks[0] : Vs[0];
        const uint32_t qb = smem_u32(&qbuf[((wid & 3) * 16) * FPITCH]) +
            (((uint32_t)(lane & 15) * FPITCH + (uint32_t)(lane >> 4) * 8) * 2);
#pragma unroll
        for (int ks = 0; ks < 4; ++ks)
            ldsm4(qf[ks], qb + (uint32_t)(ks * 16) * 2);
    }
    __syncthreads();   // all warps done reading Q before cp.async overwrites the buffers

    float of[8][4];
#pragma unroll
    for (int nt = 0; nt < 8; ++nt)
#pragma unroll
        for (int r = 0; r < 4; ++r) of[nt][r] = 0.f;
    float m0 = -1e30f, m1 = -1e30f, l0 = 0.f, l1 = 0.f;

    const int rlo = i0 + wid * 16;
    const int rhi = rlo + 15;
    const int rowA = rlo + g;
    const int rowB = rowA + 8;
    const int c0 = (i0 >= 256) ? (i0 - 256) : 0;
    const uint32_t k_loff = (((uint32_t)((lane & 7) + ((lane >> 1) & 8)) * FPITCH + (uint32_t)(lane & 8)) * 2);

    auto loadKV = [&](int c, int s) {
#pragma unroll
        for (int f = tid; f < 512; f += 256) {
            int r = f >> 3, c8 = (f & 7) * 8;
            cpa16(smem_u32(&Ks[s][r * FPITCH + c8]), K + (size_t)(c + r) * ldq + c8);
            cpa16(smem_u32(&Vs[s][r * FPITCH + c8]), V + (size_t)(c + r) * ldq + c8);
        }
    };

    loadKV(c0, 0);
    CP_COMMIT();

    const int nch = (i0 + 64 - c0) / 64 + 1;   // chunks cover cols up to i0+127
    for (int i = 0; i < nch; ++i) {
        const int c = c0 + i * 64;
        const int st = i & 1;
        if (i + 1 < nch) {
            loadKV(c + 64, st ^ 1);
            CP_COMMIT();
            cp_wait<1>();
        } else {
            cp_wait<0>();
        }
        __syncthreads();

        const uint32_t kb = smem_u32(Ks[st]) + k_loff;
        const uint32_t vb = smem_u32(Vs[st]) + lane * (FPITCH * 2);

        // ---- S = Q K^T ----
        float sc[8][4];
#pragma unroll
        for (int nt = 0; nt < 8; ++nt)
#pragma unroll
            for (int r = 0; r < 4; ++r) sc[nt][r] = 0.f;
#pragma unroll
        for (int ks = 0; ks < 4; ++ks) {
#pragma unroll
            for (int p = 0; p < 4; ++p) {
                uint32_t r[4];
                ldsm4(r, kb + (uint32_t)(p * 16 * FPITCH + ks * 16) * 2);
                mma16h(sc[2*p],   qf[ks], r);
                mma16h(sc[2*p+1], qf[ks], r + 2);
            }
        }

        // ---- scale + mask (per-warp gating, exact per-element check) ----
#pragma unroll
        for (int nt = 0; nt < 8; ++nt)
#pragma unroll
            for (int r = 0; r < 4; ++r) sc[nt][r] *= 0.125f;

        const bool mhi = (c + 63) > rlo;
        const bool mlo = c < (rhi - 256);
        if (mhi | mlo) {
#pragma unroll
            for (int nt = 0; nt < 8; ++nt) {
                int col = c + nt * 8 + 2 * t;
#pragma unroll
                for (int e = 0; e < 2; ++e) {
                    int j = col + e;
                    if (j > rowA || j < rowA - 256) sc[nt][e]     = -1e30f;
                    if (j > rowB || j < rowB - 256) sc[nt][e + 2] = -1e30f;
                }
            }
        }

        // ---- online softmax ----
        float mxA = -1e30f, mxB = -1e30f;
#pragma unroll
        for (int nt = 0; nt < 8; ++nt) {
            mxA = fmaxf(mxA, fmaxf(sc[nt][0], sc[nt][1]));
            mxB = fmaxf(mxB, fmaxf(sc[nt][2], sc[nt][3]));
        }
        mxA = fmaxf(mxA, __shfl_xor_sync(0xffffffffu, mxA, 1));
        mxA = fmaxf(mxA, __shfl_xor_sync(0xffffffffu, mxA, 2));
        mxB = fmaxf(mxB, __shfl_xor_sync(0xffffffffu, mxB, 1));
        mxB = fmaxf(mxB, __shfl_xor_sync(0xffffffffu, mxB, 2));
        float nm0 = fmaxf(m0, mxA), nm1 = fmaxf(m1, mxB);
        float e0 = __expf(m0 - nm0), e1 = __expf(m1 - nm1);
        float sA = 0.f, sB = 0.f;
#pragma unroll
        for (int nt = 0; nt < 8; ++nt) {
            sc[nt][0] = __expf(sc[nt][0] - nm0);
            sc[nt][1] = __expf(sc[nt][1] - nm0);
            sc[nt][2] = __expf(sc[nt][2] - nm1);
            sc[nt][3] = __expf(sc[nt][3] - nm1);
            sA += sc[nt][0] + sc[nt][1];
            sB += sc[nt][2] + sc[nt][3];
        }
        sA += __shfl_xor_sync(0xffffffffu, sA, 1);
        sA += __shfl_xor_sync(0xffffffffu, sA, 2);
        sB += __shfl_xor_sync(0xffffffffu, sB, 1);
        sB += __shfl_xor_sync(0xffffffffu, sB, 2);
        l0 = l0 * e0 + sA;
        l1 = l1 * e1 + sB;
        m0 = nm0; m1 = nm1;
#pragma unroll
        for (int nt = 0; nt < 8; ++nt) {
            of[nt][0] *= e0; of[nt][1] *= e0;
            of[nt][2] *= e1; of[nt][3] *= e1;
        }

        // ---- P (fp16 A-fragments, direct pack) ----
        uint32_t af[4][4];
#pragma unroll
        for (int kg = 0; kg < 4; ++kg) {
            af[kg][0] = packh2(sc[2*kg][0],   sc[2*kg][1]);
            af[kg][1] = packh2(sc[2*kg][2],   sc[2*kg][3]);
            af[kg][2] = packh2(sc[2*kg+1][0], sc[2*kg+1][1]);
            af[kg][3] = packh2(sc[2*kg+1][2], sc[2*kg+1][3]);
        }

        // ---- O += P V ----
#pragma unroll
        for (int nt = 0; nt < 8; ++nt) {
            uint32_t vf[8];
            ldsm4t(vf,     vb + nt * 16);
            ldsm4t(vf + 4, vb + 32 * (FPITCH * 2) + nt * 16);
            mma16h(of[nt], af[0], vf);
            mma16h(of[nt], af[1], vf + 2);
            mma16h(of[nt], af[2], vf + 4);
            mma16h(of[nt], af[3], vf + 6);
        }
        __syncthreads();
    }

    float r0 = 1.f / l0, r1 = 1.f / l1;
#pragma unroll
    for (int nt = 0; nt < 8; ++nt) {
        *(__half2*)(Oh + ho + (size_t)rowA * DIM + nt * 8 + 2 * t) =
            __floats2half2_rn(of[nt][0] * r0, of[nt][1] * r0);
        *(__half2*)(Oh + ho + (size_t)rowB * DIM + nt * 8 + 2 * t) =
            __floats2half2_rn(of[nt][2] * r1, of[nt][3] * r1);
    }
}

// ---------------- global cluster attention (32 tokens per batch) ----------------
__global__ __launch_bounds__(32)
void cluster_attn(const float* __restrict__ QKV, float* __restrict__ O)
{
    const int h = blockIdx.x, b = blockIdx.y;
    const int tid = threadIdx.x;
    const size_t base = (size_t)b * 32 * (3*DIM) + (size_t)h * HDIM;
    const float* Q = QKV + base;
    const float* K = QKV + base + DIM;
    const float* V = QKV + base + 2 * DIM;

    __shared__ __align__(16) float Ks[32*HDIM];
    __shared__ __align__(16) float Vs[32*HDIM];
    for (int e = tid * 4; e < 32 * HDIM; e += 32 * 4) {
        int j = e >> 6, d = e & 63;
        *(float4*)&Ks[e] = *(const float4*)(K + (size_t)j * (3*DIM) + d);
        *(float4*)&Vs[e] = *(const float4*)(V + (size_t)j * (3*DIM) + d);
    }
    __syncthreads();

    float q[HDIM];
    const float* qp = Q + (size_t)tid * (3*DIM);
#pragma unroll
    for (int d = 0; d < HDIM; ++d) q[d] = qp[d] * 0.125f;

    float s[32], mx = -1e30f;
#pragma unroll 1
    for (int j = 0; j < 32; ++j) {
        float tt = 0.f;
#pragma unroll
        for (int d = 0; d < HDIM; ++d) tt += q[d] * Ks[j*HDIM + d];
        s[j] = tt;
        if (tt > mx) mx = tt;
    }
    float lsum = 0.f;
#pragma unroll
    for (int j = 0; j < 32; ++j) { s[j] = __expf(s[j] - mx); lsum += s[j]; }
    float acc[HDIM];
#pragma unroll
    for (int d = 0; d < HDIM; ++d) acc[d] = 0.f;
#pragma unroll 1
    for (int j = 0; j < 32; ++j) {
        float p = s[j];
#pragma unroll
        for (int d = 0; d < HDIM; ++d) acc[d] += p * Vs[j*HDIM + d];
    }
    float inv = 1.f / lsum;
    float* op = O + (size_t)(b * 32 + tid) * DIM + (size_t)h * HDIM;
#pragma unroll
    for (int d = 0; d < HDIM; ++d) op[d] = acc[d] * inv;
}

// ---------------- cluster mean ----------------
__global__ void cluster_mean(const float* __restrict__ X, float* __restrict__ R)
{
    const int bc = blockIdx.x;
    const float* xp = X + (size_t)bc * 64 * DIM;
    for (int d = threadIdx.x; d < DIM; d += blockDim.x) {
        float sum = 0.f;
        for (int t = 0; t < 64; ++t) sum += xp[(size_t)t * DIM + d];
        R[(size_t)bc * DIM + d] = sum * (1.f / 64.f);
    }
}

// ---------------- mlp_in = reps_sum(batch) - reps ----------------
__global__ void cluster_diff(const float* __restrict__ R, float* __restrict__ Mi)
{
    const int b = blockIdx.x;
    const int d = threadIdx.x;
    float sum = 0.f;
    for (int c = 0; c < 32; ++c) sum += R[(size_t)(b*32 + c) * DIM + d];
    for (int c = 0; c < 32; ++c)
        Mi[(size_t)(b*32 + c) * DIM + d] = sum - R[(size_t)(b*32 + c) * DIM + d];
}

// ---------------- host ----------------
static void* symp(const void* symbol) {
    void* p = nullptr;
    cudaGetSymbolAddress(&p, symbol);
    return p;
}

extern "C" void kernel_launch(void* const* d_in, const int* in_sizes, int n_in,
                              void* d_out, int out_size)
{
    const float* x   = (const float*)d_in[0];
    const float* lqw = (const float*)d_in[1];
    const float* lqb = (const float*)d_in[2];
    const float* lkw = (const float*)d_in[3];
    const float* lkb = (const float*)d_in[4];
    const float* lvw = (const float*)d_in[5];
    const float* lvb = (const float*)d_in[6];
    const float* low = (const float*)d_in[7];
    const float* lob = (const float*)d_in[8];
    const float* m1w = (const float*)d_in[9];
    const float* m1b = (const float*)d_in[10];
    const float* m2w = (const float*)d_in[11];
    const float* m2b = (const float*)d_in[12];
    const float* gqw = (const float*)d_in[13];
    const float* gqb = (const float*)d_in[14];
    const float* gkw = (const float*)d_in[15];
    const float* gkb = (const float*)d_in[16];
    const float* gvw = (const float*)d_in[17];
    const float* gvb = (const float*)d_in[18];
    const float* gow = (const float*)d_in[19];
    const float* gob = (const float*)d_in[20];
    const float* g1w = (const float*)d_in[21];
    const float* g1b = (const float*)d_in[22];
    const float* g2w = (const float*)d_in[23];
    const float* g2b = (const float*)d_in[24];
    float* out = (float*)d_out;

    float* h1    = (float*)symp(g_h1);
    float* h2    = (float*)symp(g_h2);
    float* reps  = (float*)symp(s_reps);
    float* mlpin = (float*)symp(s_mlpin);
    float* t1    = (float*)symp(s_t1);
    float* mix   = (float*)symp(s_mix);
    float* rqkv  = (float*)symp(s_rqkv);
    float* ratt  = (float*)symp(s_ratt);
    float* rnew  = (float*)symp(s_rnew);
    float* gproj = (float*)symp(s_gproj);
    float* gqkvw = (float*)symp(w_gqkv);
    float* gqkvb = (float*)symp(b_gqkv);
    float* qkvb  = (float*)symp(b_qkv);

    __half* hqkv = (__half*)symp(w_qkv);
    __half* hlo  = (__half*)symp(w_lo);
    __half* hg1  = (__half*)symp(w_g1);
    __half* hg2  = (__half*)symp(w_g2);
    __half* xh   = (__half*)symp(a_x);
    __half* qkvh = (__half*)symp(a_qkv);
    __half* atth = (__half*)symp(a_att);
    __half* h1h  = (__half*)symp(a_h1);
    __half* h2h  = (__half*)symp(a_h2);
    __half* hidh = (__half*)symp(a_hid);

    auto gemm_plain = gemm_h<false>;
    auto gemm_merge = gemm_h<true>;
    cudaFuncSetAttribute(gemm_plain, cudaFuncAttributeMaxDynamicSharedMemorySize, GEMM_H_SMEM);
    cudaFuncSetAttribute(gemm_merge, cudaFuncAttributeMaxDynamicSharedMemorySize, GEMM_H_SMEM);
    auto gemm_sm = gemm_mma<64,64,32,16,2>;
    cudaFuncSetAttribute(gemm_sm, cudaFuncAttributeMaxDynamicSharedMemorySize, GEMM_SMEM_SM);

    // ---- conversions + packs (two launches) ----
    {
        CvtArgs ca;
        ca.src[0] = x;        ca.dst[0] = xh;          ca.n[0] = TOKENS*DIM;
        ca.src[1] = lqw;      ca.dst[1] = hqkv;        ca.n[1] = (int)DD;
        ca.src[2] = lkw;      ca.dst[2] = hqkv + DD;   ca.n[2] = (int)DD;
        ca.src[3] = lvw;      ca.dst[3] = hqkv + 2*DD; ca.n[3] = (int)DD;
        ca.src[4] = lqw + DD; ca.dst[4] = hqkv + 3*DD; ca.n[4] = (int)DD;
        ca.src[5] = lkw + DD; ca.dst[5] = hqkv + 4*DD; ca.n[5] = (int)DD;
        ca.src[6] = lvw + DD; ca.dst[6] = hqkv + 5*DD; ca.n[6] = (int)DD;
        ca.src[7] = low;      ca.dst[7] = hlo;         ca.n[7] = (int)(2*DD);
        ca.src[8] = g1w;      ca.dst[8] = hg1;         ca.n[8] = (int)(2*DD);
        ca.src[9] = g2w;      ca.dst[9] = hg2;         ca.n[9] = (int)DD;
        f2h_kernel<<<dim3(256, 10), 256>>>(ca);
    }
    {
        PackArgs pa;
        pa.src[0] = gqw;         pa.dst[0] = gqkvw;         pa.n[0] = (int)DD;
        pa.src[1] = gkw;         pa.dst[1] = gqkvw + DD;    pa.n[1] = (int)DD;
        pa.src[2] = gvw;         pa.dst[2] = gqkvw + 2*DD;  pa.n[2] = (int)DD;
        pa.src[3] = gqb;         pa.dst[3] = gqkvb;         pa.n[3] = DIM;
        pa.src[4] = gkb;         pa.dst[4] = gqkvb + DIM;   pa.n[4] = DIM;
        pa.src[5] = gvb;         pa.dst[5] = gqkvb + 2*DIM; pa.n[5] = DIM;
        pa.src[6] = lqb;         pa.dst[6] = qkvb;          pa.n[6] = DIM;
        pa.src[7] = lkb;         pa.dst[7] = qkvb + DIM;    pa.n[7] = DIM;
        pa.src[8] = lvb;         pa.dst[8] = qkvb + 2*DIM;  pa.n[8] = DIM;
        pa.src[9] = lqb + DIM;   pa.dst[9] = qkvb + 3*DIM;  pa.n[9] = DIM;
        pa.src[10]= lkb + DIM;   pa.dst[10]= qkvb + 4*DIM;  pa.n[10]= DIM;
        pa.src[11]= lvb + DIM;   pa.dst[11]= qkvb + 5*DIM;  pa.n[11]= DIM;
        packf_kernel<<<dim3(64, 12), 256>>>(pa);
    }

    const dim3 gQKV(3*DIM/128, TOKENS/128);   // 24 x 32
    const dim3 gBig(DIM/128, TOKENS/128);     // 8 x 32
    const dim3 gSm (DIM/64, 1);               // 16 x 1
    const dim3 gSm3(3*DIM/64, 1);             // 48 x 1
    const dim3 gAtt(SEQ/128, HEADS, BATCH);   // 16 x 16 x 2
    const dim3 gCAtt(HEADS, BATCH);

    // ---- local layer 0 ----
    gemm_plain<<<gQKV, 256, GEMM_H_SMEM>>>(xh, hqkv, DIM, qkvb, nullptr, 1, 0, nullptr, qkvh, TOKENS, 3*DIM, DIM, 0, nullptr);
    flash_attn_h<<<gAtt, 256>>>(qkvh, 3*DIM, atth);
    gemm_plain<<<gBig, 256, GEMM_H_SMEM>>>(atth, hlo, DIM, lob, x, 1, DIM, h1, h1h, TOKENS, DIM, DIM, 0, nullptr);

    // ---- local layer 1 ----
    gemm_plain<<<gQKV, 256, GEMM_H_SMEM>>>(h1h, hqkv + 3*DD, DIM, qkvb + 3*DIM, nullptr, 1, 0, nullptr, qkvh, TOKENS, 3*DIM, DIM, 0, nullptr);
    flash_attn_h<<<gAtt, 256>>>(qkvh, 3*DIM, atth);
    gemm_plain<<<gBig, 256, GEMM_H_SMEM>>>(atth, hlo + DD, DIM, lob + DIM, h1, 1, DIM, h2, h2h, TOKENS, DIM, DIM, 0, nullptr);
    // h2 = x_local (fp32) / h2h (fp16)

    // ---- cluster path ----
    cluster_mean<<<NCLUST, 256>>>(h2, reps);
    cluster_diff<<<BATCH, DIM>>>(reps, mlpin);
    gemm_sm<<<gSm, 256, GEMM_SMEM_SM>>>(mlpin, m1w, DIM, m1b, nullptr, 1, t1, NCLUST, DIM, DIM, 1);
    gemm_sm<<<gSm, 256, GEMM_SMEM_SM>>>(t1, m2w, DIM, m2b, reps, 1, mix, NCLUST, DIM, DIM, 0);
    gemm_sm<<<gSm3, 256, GEMM_SMEM_SM>>>(mix, gqkvw, DIM, gqkvb, nullptr, 1, rqkv, NCLUST, 3*DIM, DIM, 0);
    cluster_attn<<<gCAtt, 32>>>(rqkv, ratt);
    gemm_sm<<<gSm, 256, GEMM_SMEM_SM>>>(ratt, gow, DIM, gob, nullptr, 1, rnew, NCLUST, DIM, DIM, 0);

    // gproj = reps_new @ W1b^T (second half of g1w columns, ldb = 2*DIM)
    gemm_sm<<<gSm, 256, GEMM_SMEM_SM>>>(rnew, g1w + DIM, 2*DIM, nullptr, nullptr, 1, gproj, NCLUST, DIM, DIM, 0);

    // hidden = gelu(x_local @ W1a^T + g1b + broadcast(gproj))
    gemm_plain<<<gBig, 256, GEMM_H_SMEM>>>(h2h, hg1, 2*DIM, g1b, gproj, 64, DIM, nullptr, hidh, TOKENS, DIM, DIM, 1, nullptr);
    // out = x_local + sigmoid(hidden @ g2w^T + g2b) * (broadcast(rnew) - x_local)   [fused, dedicated kernel]
    gemm_merge<<<gBig, 256, GEMM_H_SMEM>>>(hidh, hg2, DIM, g2b, rnew, 64, DIM, out, nullptr, TOKENS, DIM, DIM, 3, h2);
}

// round 16
// speedup vs baseline: 1.0065x; 1.0065x over previous
#include <cuda_runtime.h>
#include <cuda_fp16.h>
#include <math.h>
#include <stdint.h>

#define BATCH 2
#define SEQ   2048
#define DIM   1024
#define HEADS 16
#define HDIM  64
#define TOKENS (BATCH*SEQ)        /* 4096 */
#define NCLUST 64                 /* B*C = 2*32 */
#define DD ((size_t)DIM*DIM)

// ---------------- scratch (static device arrays; no allocations) ----------------
__device__ float g_h1 [(size_t)TOKENS*DIM];
__device__ float g_h2 [(size_t)TOKENS*DIM];

__device__ float s_reps [NCLUST*DIM];
__device__ float s_mlpin[NCLUST*DIM];
__device__ float s_t1   [NCLUST*DIM];
__device__ float s_mix  [NCLUST*DIM];
__device__ float s_rqkv [NCLUST*3*DIM];
__device__ float s_ratt [NCLUST*DIM];
__device__ float s_rnew [NCLUST*DIM];
__device__ float s_gproj[NCLUST*DIM];

__device__ float w_gqkv[3*DD];
__device__ float b_gqkv[3*DIM];
__device__ float b_qkv [2*3*DIM];

// fp16 buffers
__device__ __half w_qkv[6*DD];
__device__ __half w_lo[2*DD];
__device__ __half w_g1[2*DD];
__device__ __half w_g2[DD];
__device__ __half a_x   [(size_t)TOKENS*DIM];
__device__ __half a_qkv [(size_t)TOKENS*3*DIM];
__device__ __half a_att [(size_t)TOKENS*DIM];
__device__ __half a_h1  [(size_t)TOKENS*DIM];
__device__ __half a_h2  [(size_t)TOKENS*DIM];
__device__ __half a_hid [(size_t)TOKENS*DIM];

// ---------------- PTX helpers ----------------
__device__ __forceinline__ uint32_t smem_u32(const void* p) {
    uint32_t a;
    asm("{ .reg .u64 t; cvta.to.shared.u64 t, %1; cvt.u32.u64 %0, t; }" : "=r"(a) : "l"(p));
    return a;
}
__device__ __forceinline__ void cpa16(uint32_t saddr, const void* g) {
    asm volatile("cp.async.cg.shared.global [%0], [%1], 16;" :: "r"(saddr), "l"(g));
}
#define CP_COMMIT() asm volatile("cp.async.commit_group;" ::: "memory")
template<int N>
__device__ __forceinline__ void cp_wait() {
    asm volatile("cp.async.wait_group %0;" :: "n"(N) : "memory");
}
__device__ __forceinline__ uint32_t cvt_tf32(float v) {
    uint32_t r;
    asm("cvt.rna.tf32.f32 %0, %1;" : "=r"(r) : "f"(v));
    return r;
}
__device__ __forceinline__ void mma8(float* c, const uint32_t* a, const uint32_t* b) {
    asm volatile(
        "mma.sync.aligned.m16n8k8.row.col.f32.tf32.tf32.f32 "
        "{%0,%1,%2,%3}, {%4,%5,%6,%7}, {%8,%9}, {%0,%1,%2,%3};"
        : "+f"(c[0]), "+f"(c[1]), "+f"(c[2]), "+f"(c[3])
        : "r"(a[0]), "r"(a[1]), "r"(a[2]), "r"(a[3]), "r"(b[0]), "r"(b[1]));
}
__device__ __forceinline__ void mma16h(float* c, const uint32_t* a, const uint32_t* b) {
    asm volatile(
        "mma.sync.aligned.m16n8k16.row.col.f32.f16.f16.f32 "
        "{%0,%1,%2,%3}, {%4,%5,%6,%7}, {%8,%9}, {%0,%1,%2,%3};"
        : "+f"(c[0]), "+f"(c[1]), "+f"(c[2]), "+f"(c[3])
        : "r"(a[0]), "r"(a[1]), "r"(a[2]), "r"(a[3]), "r"(b[0]), "r"(b[1]));
}
__device__ __forceinline__ void ldsm4(uint32_t* r, uint32_t saddr) {
    asm volatile("ldmatrix.sync.aligned.m8n8.x4.shared.b16 {%0,%1,%2,%3}, [%4];"
        : "=r"(r[0]), "=r"(r[1]), "=r"(r[2]), "=r"(r[3]) : "r"(saddr));
}
__device__ __forceinline__ void ldsm4t(uint32_t* r, uint32_t saddr) {
    asm volatile("ldmatrix.sync.aligned.m8n8.x4.trans.shared.b16 {%0,%1,%2,%3}, [%4];"
        : "=r"(r[0]), "=r"(r[1]), "=r"(r[2]), "=r"(r[3]) : "r"(saddr));
}
__device__ __forceinline__ uint32_t packh2(float a, float b) {
    __half2 h = __floats2half2_rn(a, b);
    return *(uint32_t*)&h;
}

// ---------------- epilogue (act: 0 none, 1 gelu, 2 sigmoid) ----------------
__device__ __forceinline__ float epilogue(float v, int m, int n,
                                          const float* __restrict__ bias,
                                          const float* __restrict__ add, int addDiv,
                                          int addLd, int act) {
    if (bias) v += bias[n];
    if (add)  v += add[(size_t)(m / addDiv) * addLd + n];
    if (act == 1) {
        v = 0.5f * v * (1.0f + erff(v * 0.70710678118654752f));
    } else if (act == 2) {
        v = 1.0f / (1.0f + expf(-v));
    }
    return v;
}

// ---------------- fp32 -> fp16 bulk conversion (single launch, 10 segments) ----------------
struct CvtArgs {
    const float* src[10];
    __half* dst[10];
    int n[10];
};
__global__ void f2h_kernel(CvtArgs args) {
    const int seg = blockIdx.y;
    const int n4 = args.n[seg] >> 2;
    const float4* s = (const float4*)args.src[seg];
    __half2* d = (__half2*)args.dst[seg];
    for (int i = blockIdx.x * blockDim.x + threadIdx.x; i < n4; i += gridDim.x * blockDim.x) {
        float4 v = s[i];
        d[2*i]   = __floats2half2_rn(v.x, v.y);
        d[2*i+1] = __floats2half2_rn(v.z, v.w);
    }
}

// ---------------- fp32 pack copies (single launch, 12 segments) ----------------
struct PackArgs {
    const float* src[12];
    float* dst[12];
    int n[12];
};
__global__ void packf_kernel(PackArgs args) {
    const int seg = blockIdx.y;
    const int n4 = args.n[seg] >> 2;
    const float4* s = (const float4*)args.src[seg];
    float4* d = (float4*)args.dst[seg];
    for (int i = blockIdx.x * blockDim.x + threadIdx.x; i < n4; i += gridDim.x * blockDim.x)
        d[i] = s[i];
}

// ---------------- fp16 mma GEMM: C[M,N] = A[M,K] * B[N,K]^T (+bias,+add,act) ----------------
// 128x128 CTA tile, 8 warps (2x4), warp tile 64x32, BK=32, 4-stage cp.async. (R9/R11 proven)
// MERGE=true: final-gate variant — C = XL + sigmoid(v+bias) * (add_bcast - XL).
#define HPITCH 40
#define HSTAGES 4
#define GEMM_H_SMEM (HSTAGES * 2 * 128 * HPITCH * 2)   /* 81920 */

template<bool MERGE>
__global__ __launch_bounds__(256, 2)
void gemm_h(const __half* __restrict__ A,
            const __half* __restrict__ B, int ldb,
            const float* __restrict__ bias,
            const float* __restrict__ add, int addDiv, int addLd,
            float* __restrict__ C, __half* __restrict__ Ch,
            int M, int Nn, int K, int act,
            const float* __restrict__ XL)
{
    extern __shared__ __half hsm[];
    __half* Asm = hsm;
    __half* Bsm = hsm + HSTAGES * 128 * HPITCH;

    const int tid  = threadIdx.x;
    const int wid  = tid >> 5;
    const int lane = tid & 31;
    const int warp_m = wid >> 2;     // 0..1
    const int warp_n = wid & 3;      // 0..3
    const int m0 = blockIdx.y * 128;
    const int n0 = blockIdx.x * 128;
    const int g = lane >> 2;
    const int t = lane & 3;

    const uint32_t a_loff = ((uint32_t)(lane & 15) * HPITCH + (uint32_t)(lane >> 4) * 8) * 2;
    const uint32_t b_row  = (uint32_t)(lane & 7) + (uint32_t)((lane >> 1) & 8);
    const uint32_t b_loff = (b_row * HPITCH + (uint32_t)(lane & 8)) * 2;

    float acc[4][4][4];
#pragma unroll
    for (int mi = 0; mi < 4; ++mi)
#pragma unroll
        for (int ni = 0; ni < 4; ++ni)
#pragma unroll
            for (int r = 0; r < 4; ++r) acc[mi][ni][r] = 0.f;

    auto load = [&](int kc, int s) {
        const int k0 = kc * 32;
        __half* da = Asm + s * 128 * HPITCH;
        __half* db = Bsm + s * 128 * HPITCH;
#pragma unroll
        for (int f = tid; f < 512; f += 256) {
            int r = f >> 2, c = f & 3;
            int am = m0 + r; if (am > M - 1) am = M - 1;
            cpa16(smem_u32(da + r * HPITCH + c * 8), A + (size_t)am * K + k0 + c * 8);
        }
#pragma unroll
        for (int f = tid; f < 512; f += 256) {
            int r = f >> 2, c = f & 3;
            cpa16(smem_u32(db + r * HPITCH + c * 8), B + (size_t)(n0 + r) * ldb + k0 + c * 8);
        }
    };

    auto compute = [&](int s) {
        const uint32_t abase = smem_u32(Asm + s * 128 * HPITCH + warp_m * 64 * HPITCH) + a_loff;
        const uint32_t bbase = smem_u32(Bsm + s * 128 * HPITCH + warp_n * 32 * HPITCH) + b_loff;
#pragma unroll
        for (int ks = 0; ks < 2; ++ks) {
            uint32_t af[4][4], bf[4][2];
#pragma unroll
            for (int mi = 0; mi < 4; ++mi)
                ldsm4(af[mi], abase + (uint32_t)(mi * 16 * HPITCH + ks * 16) * 2);
#pragma unroll
            for (int p = 0; p < 2; ++p) {
                uint32_t r[4];
                ldsm4(r, bbase + (uint32_t)(p * 16 * HPITCH + ks * 16) * 2);
                bf[2*p][0] = r[0]; bf[2*p][1] = r[1];
                bf[2*p+1][0] = r[2]; bf[2*p+1][1] = r[3];
            }
#pragma unroll
            for (int mi = 0; mi < 4; ++mi)
#pragma unroll
                for (int ni = 0; ni < 4; ++ni)
                    mma16h(acc[mi][ni], af[mi], bf[ni]);
        }
    };

    const int NC = K >> 5;
#pragma unroll
    for (int s = 0; s < HSTAGES - 1; ++s) {
        if (s < NC) load(s, s);
        CP_COMMIT();
    }
    for (int kc = 0; kc < NC; ++kc) {
        if (kc + HSTAGES - 1 < NC) {
            load(kc + HSTAGES - 1, (kc + HSTAGES - 1) & (HSTAGES - 1));
            CP_COMMIT();
            cp_wait<HSTAGES - 1>();
        } else {
            cp_wait<0>();
        }
        __syncthreads();
        compute(kc & (HSTAGES - 1));
        __syncthreads();
    }

#pragma unroll
    for (int mi = 0; mi < 4; ++mi) {
#pragma unroll
        for (int ni = 0; ni < 4; ++ni) {
            int row = m0 + warp_m * 64 + mi * 16 + g;
            int col = n0 + warp_n * 32 + ni * 8 + 2 * t;
#pragma unroll
            for (int half_ = 0; half_ < 2; ++half_) {
                int rr = row + half_ * 8;
                if (rr >= M) continue;
                if (MERGE) {
                    float2 o;
#pragma unroll
                    for (int e = 0; e < 2; ++e) {
                        float v = acc[mi][ni][half_*2 + e] + bias[col + e];
                        float sx = 1.f / (1.f + expf(-v));
                        float xl = XL[(size_t)rr * Nn + col + e];
                        float xg = add[(size_t)(rr / addDiv) * addLd + col + e];
                        ((float*)&o)[e] = xl + sx * (xg - xl);
                    }
                    *(float2*)&C[(size_t)rr * Nn + col] = o;
                } else {
                    float vx = epilogue(acc[mi][ni][half_*2],   rr, col,     bias, add, addDiv, addLd, act);
                    float vy = epilogue(acc[mi][ni][half_*2+1], rr, col + 1, bias, add, addDiv, addLd, act);
                    if (C)  *(float2*)&C[(size_t)rr * Nn + col] = make_float2(vx, vy);
                    if (Ch) *(__half2*)&Ch[(size_t)rr * Nn + col] = __floats2half2_rn(vx, vy);
                }
            }
        }
    }
}

// ---------------- tf32 mma.sync GEMM (small cluster chain), BK=64, 2 stages (R11 proven) ----------------
#define SPITCH 68

template<int BM, int BN, int WM, int WN, int NSTAGE>
__global__ __launch_bounds__(256, 3)
void gemm_mma(const float* __restrict__ A,
              const float* __restrict__ B, int ldb,
              const float* __restrict__ bias,
              const float* __restrict__ add, int addDiv,
              float* __restrict__ C, int M, int Nn, int K, int act)
{
    constexpr int MI  = WM / 16;
    constexpr int NI  = WN / 8;
    constexpr int WGN = BN / WN;

    extern __shared__ float sm[];
    float* Asm = sm;
    float* Bsm = sm + NSTAGE * BM * SPITCH;

    const int tid  = threadIdx.x;
    const int wid  = tid >> 5;
    const int lane = tid & 31;
    const int warp_m = wid / WGN;
    const int warp_n = wid % WGN;
    const int m0 = blockIdx.y * BM;
    const int n0 = blockIdx.x * BN;
    const int g = lane >> 2;
    const int t = lane & 3;

    float acc[MI][NI][4];
#pragma unroll
    for (int mi = 0; mi < MI; ++mi)
#pragma unroll
        for (int ni = 0; ni < NI; ++ni)
#pragma unroll
            for (int r = 0; r < 4; ++r) acc[mi][ni][r] = 0.f;

    auto load = [&](int kc, int s) {
        const int k0 = kc * 64;
        float* da = Asm + s * BM * SPITCH;
        float* db = Bsm + s * BN * SPITCH;
#pragma unroll
        for (int f = tid; f < BM * 16; f += 256) {
            int r = f >> 4, c4 = f & 15;
            int am = m0 + r; if (am > M - 1) am = M - 1;
            cpa16(smem_u32(da + r * SPITCH + c4 * 4), A + (size_t)am * K + k0 + c4 * 4);
        }
#pragma unroll
        for (int f = tid; f < BN * 16; f += 256) {
            int r = f >> 4, c4 = f & 15;
            cpa16(smem_u32(db + r * SPITCH + c4 * 4), B + (size_t)(n0 + r) * ldb + k0 + c4 * 4);
        }
    };

    auto compute = [&](int s) {
        const float* da = Asm + s * BM * SPITCH + (size_t)warp_m * WM * SPITCH;
        const float* db = Bsm + s * BN * SPITCH + (size_t)warp_n * WN * SPITCH;
#pragma unroll
        for (int ks = 0; ks < 8; ++ks) {
            uint32_t af[MI][4], bf[NI][2];
#pragma unroll
            for (int mi = 0; mi < MI; ++mi) {
                const float* p = da + (mi * 16 + g) * SPITCH + ks * 8 + t;
                af[mi][0] = cvt_tf32(p[0]);
                af[mi][1] = cvt_tf32(p[8 * SPITCH]);
                af[mi][2] = cvt_tf32(p[4]);
                af[mi][3] = cvt_tf32(p[8 * SPITCH + 4]);
            }
#pragma unroll
            for (int ni = 0; ni < NI; ++ni) {
                const float* p = db + (ni * 8 + g) * SPITCH + ks * 8 + t;
                bf[ni][0] = cvt_tf32(p[0]);
                bf[ni][1] = cvt_tf32(p[4]);
            }
#pragma unroll
            for (int mi = 0; mi < MI; ++mi)
#pragma unroll
                for (int ni = 0; ni < NI; ++ni)
                    mma8(acc[mi][ni], af[mi], bf[ni]);
        }
    };

    const int NC = K >> 6;
#pragma unroll
    for (int s = 0; s < NSTAGE - 1; ++s) {
        if (s < NC) load(s, s);
        CP_COMMIT();
    }
    for (int kc = 0; kc < NC; ++kc) {
        if (kc + NSTAGE - 1 < NC) {
            load(kc + NSTAGE - 1, (kc + NSTAGE - 1) % NSTAGE);
            CP_COMMIT();
            cp_wait<NSTAGE - 1>();
        } else {
            cp_wait<0>();
        }
        __syncthreads();
        compute(kc % NSTAGE);
        __syncthreads();
    }

#pragma unroll
    for (int mi = 0; mi < MI; ++mi) {
#pragma unroll
        for (int ni = 0; ni < NI; ++ni) {
            int row = m0 + warp_m * WM + mi * 16 + g;
            int col = n0 + warp_n * WN + ni * 8 + 2 * t;
            if (row < M) {
                float2 v0;
                v0.x = epilogue(acc[mi][ni][0], row, col,     bias, add, addDiv, Nn, act);
                v0.y = epilogue(acc[mi][ni][1], row, col + 1, bias, add, addDiv, Nn, act);
                *(float2*)&C[(size_t)row * Nn + col] = v0;
            }
            if (row + 8 < M) {
                float2 v1;
                v1.x = epilogue(acc[mi][ni][2], row + 8, col,     bias, add, addDiv, Nn, act);
                v1.y = epilogue(acc[mi][ni][3], row + 8, col + 1, bias, add, addDiv, Nn, act);
                *(float2*)&C[(size_t)(row + 8) * Nn + col] = v1;
            }
        }
    }
}

#define GEMM_SMEM_SM  (2*(64+64)*SPITCH*4)    /* 69632 */

// ---------------- flash attention (windowed causal), full fp16 mma ----------------
// 128 queries/block, 8 warps (256 threads), 64-key K/V chunks double-buffered,
// per-warp chunk skip (warps compute only chunks intersecting their 16-row window).
#define FPITCH 72

__global__ __launch_bounds__(256, 2)
void flash_attn_h(const __half* __restrict__ QKV, int ldq, __half* __restrict__ Oh)
{
    const int i0 = blockIdx.x * 128;
    const int h = blockIdx.y, b = blockIdx.z;
    const size_t hb = (size_t)b * SEQ * ldq + (size_t)h * HDIM;
    const size_t ho = (size_t)b * SEQ * DIM + (size_t)h * HDIM;
    const __half* Q = QKV + hb;
    const __half* K = QKV + hb + DIM;
    const __half* V = QKV + hb + 2 * DIM;
    const int tid = threadIdx.x;
    const int wid = tid >> 5;     // 0..7 -> query rows wid*16..wid*16+15
    const int lane = tid & 31;
    const int g = lane >> 2;
    const int t = lane & 3;

    __shared__ __align__(16) __half Ks[2][64 * FPITCH];
    __shared__ __align__(16) __half Vs[2][64 * FPITCH];

    // ---- stage Q tile (128 rows: 0-63 in Ks[0], 64-127 in Vs[0]), build fragments ----
    for (int e = tid; e < 1024; e += 256) {
        int r = e >> 3, c8 = (e & 7) * 8;
        float4 qv = *(const float4*)(Q + (size_t)(i0 + r) * ldq + c8);
        if (r < 64) *(float4*)&Ks[0][r * FPITCH + c8] = qv;
        else        *(float4*)&Vs[0][(r - 64) * FPITCH + c8] = qv;
    }
    __syncthreads();
    uint32_t qf[4][4];
    {
        const __half* qbuf = (wid < 4) ? Ks[0] : Vs[0];
        const uint32_t qb = smem_u32(&qbuf[((wid & 3) * 16) * FPITCH]) +
            (((uint32_t)(lane & 15) * FPITCH + (uint32_t)(lane >> 4) * 8) * 2);
#pragma unroll
        for (int ks = 0; ks < 4; ++ks)
            ldsm4(qf[ks], qb + (uint32_t)(ks * 16) * 2);
    }
    __syncthreads();   // all warps done reading Q before cp.async overwrites the buffers

    float of[8][4];
#pragma unroll
    for (int nt = 0; nt < 8; ++nt)
#pragma unroll
        for (int r = 0; r < 4; ++r) of[nt][r] = 0.f;
    float m0 = -1e30f, m1 = -1e30f, l0 = 0.f, l1 = 0.f;

    const int rlo = i0 + wid * 16;
    const int rhi = rlo + 15;
    const int rowA = rlo + g;
    const int rowB = rowA + 8;
    const int c0 = (i0 >= 256) ? (i0 - 256) : 0;
    const uint32_t k_loff = (((uint32_t)((lane & 7) + ((lane >> 1) & 8)) * FPITCH + (uint32_t)(lane & 8)) * 2);

    auto loadKV = [&](int c, int s) {
#pragma unroll
        for (int f = tid; f < 512; f += 256) {
            int r = f >> 3, c8 = (f & 7) * 8;
            cpa16(smem_u32(&Ks[s][r * FPITCH + c8]), K + (size_t)(c + r) * ldq + c8);
            cpa16(smem_u32(&Vs[s][r * FPITCH + c8]), V + (size_t)(c + r) * ldq + c8);
        }
    };

    loadKV(c0, 0);
    CP_COMMIT();

    const int nch = (i0 + 64 - c0) / 64 + 1;   // chunks cover cols up to i0+127
    for (int i = 0; i < nch; ++i) {
        const int c = c0 + i * 64;
        const int st = i & 1;
        if (i + 1 < nch) {
            loadKV(c + 64, st ^ 1);
            CP_COMMIT();
            cp_wait<1>();
        } else {
            cp_wait<0>();
        }
        __syncthreads();

        // ---- per-warp chunk skip: only compute if chunk intersects this warp's window ----
        if (c <= rhi && c + 63 >= rlo - 256) {
            const uint32_t kb = smem_u32(Ks[st]) + k_loff;
            const uint32_t vb = smem_u32(Vs[st]) + lane * (FPITCH * 2);

            // ---- S = Q K^T ----
            float sc[8][4];
#pragma unroll
            for (int nt = 0; nt < 8; ++nt)
#pragma unroll
                for (int r = 0; r < 4; ++r) sc[nt][r] = 0.f;
#pragma unroll
            for (int ks = 0; ks < 4; ++ks) {
#pragma unroll
                for (int p = 0; p < 4; ++p) {
                    uint32_t r[4];
                    ldsm4(r, kb + (uint32_t)(p * 16 * FPITCH + ks * 16) * 2);
                    mma16h(sc[2*p],   qf[ks], r);
                    mma16h(sc[2*p+1], qf[ks], r + 2);
                }
            }

            // ---- scale + mask ----
#pragma unroll
            for (int nt = 0; nt < 8; ++nt)
#pragma unroll
                for (int r = 0; r < 4; ++r) sc[nt][r] *= 0.125f;

            const bool mhi = (c + 63) > rlo;
            const bool mlo = c < (rhi - 256);
            if (mhi | mlo) {
#pragma unroll
                for (int nt = 0; nt < 8; ++nt) {
                    int col = c + nt * 8 + 2 * t;
#pragma unroll
                    for (int e = 0; e < 2; ++e) {
                        int j = col + e;
                        if (j > rowA || j < rowA - 256) sc[nt][e]     = -1e30f;
                        if (j > rowB || j < rowB - 256) sc[nt][e + 2] = -1e30f;
                    }
                }
            }

            // ---- online softmax ----
            float mxA = -1e30f, mxB = -1e30f;
#pragma unroll
            for (int nt = 0; nt < 8; ++nt) {
                mxA = fmaxf(mxA, fmaxf(sc[nt][0], sc[nt][1]));
                mxB = fmaxf(mxB, fmaxf(sc[nt][2], sc[nt][3]));
            }
            mxA = fmaxf(mxA, __shfl_xor_sync(0xffffffffu, mxA, 1));
            mxA = fmaxf(mxA, __shfl_xor_sync(0xffffffffu, mxA, 2));
            mxB = fmaxf(mxB, __shfl_xor_sync(0xffffffffu, mxB, 1));
            mxB = fmaxf(mxB, __shfl_xor_sync(0xffffffffu, mxB, 2));
            float nm0 = fmaxf(m0, mxA), nm1 = fmaxf(m1, mxB);
            float e0 = __expf(m0 - nm0), e1 = __expf(m1 - nm1);
            float sA = 0.f, sB = 0.f;
#pragma unroll
            for (int nt = 0; nt < 8; ++nt) {
                sc[nt][0] = __expf(sc[nt][0] - nm0);
                sc[nt][1] = __expf(sc[nt][1] - nm0);
                sc[nt][2] = __expf(sc[nt][2] - nm1);
                sc[nt][3] = __expf(sc[nt][3] - nm1);
                sA += sc[nt][0] + sc[nt][1];
                sB += sc[nt][2] + sc[nt][3];
            }
            sA += __shfl_xor_sync(0xffffffffu, sA, 1);
            sA += __shfl_xor_sync(0xffffffffu, sA, 2);
            sB += __shfl_xor_sync(0xffffffffu, sB, 1);
            sB += __shfl_xor_sync(0xffffffffu, sB, 2);
            l0 = l0 * e0 + sA;
            l1 = l1 * e1 + sB;
            m0 = nm0; m1 = nm1;
#pragma unroll
            for (int nt = 0; nt < 8; ++nt) {
                of[nt][0] *= e0; of[nt][1] *= e0;
                of[nt][2] *= e1; of[nt][3] *= e1;
            }

            // ---- P (fp16 A-fragments, direct pack) ----
            uint32_t af[4][4];
#pragma unroll
            for (int kg = 0; kg < 4; ++kg) {
                af[kg][0] = packh2(sc[2*kg][0],   sc[2*kg][1]);
                af[kg][1] = packh2(sc[2*kg][2],   sc[2*kg][3]);
                af[kg][2] = packh2(sc[2*kg+1][0], sc[2*kg+1][1]);
                af[kg][3] = packh2(sc[2*kg+1][2], sc[2*kg+1][3]);
            }

            // ---- O += P V ----
#pragma unroll
            for (int nt = 0; nt < 8; ++nt) {
                uint32_t vf[8];
                ldsm4t(vf,     vb + nt * 16);
                ldsm4t(vf + 4, vb + 32 * (FPITCH * 2) + nt * 16);
                mma16h(of[nt], af[0], vf);
                mma16h(of[nt], af[1], vf + 2);
                mma16h(of[nt], af[2], vf + 4);
                mma16h(of[nt], af[3], vf + 6);
            }
        }
        __syncthreads();
    }

    float r0 = 1.f / l0, r1 = 1.f / l1;
#pragma unroll
    for (int nt = 0; nt < 8; ++nt) {
        *(__half2*)(Oh + ho + (size_t)rowA * DIM + nt * 8 + 2 * t) =
            __floats2half2_rn(of[nt][0] * r0, of[nt][1] * r0);
        *(__half2*)(Oh + ho + (size_t)rowB * DIM + nt * 8 + 2 * t) =
            __floats2half2_rn(of[nt][2] * r1, of[nt][3] * r1);
    }
}

// ---------------- global cluster attention (32 tokens per batch) ----------------
__global__ __launch_bounds__(32)
void cluster_attn(const float* __restrict__ QKV, float* __restrict__ O)
{
    const int h = blockIdx.x, b = blockIdx.y;
    const int tid = threadIdx.x;
    const size_t base = (size_t)b * 32 * (3*DIM) + (size_t)h * HDIM;
    const float* Q = QKV + base;
    const float* K = QKV + base + DIM;
    const float* V = QKV + base + 2 * DIM;

    __shared__ __align__(16) float Ks[32*HDIM];
    __shared__ __align__(16) float Vs[32*HDIM];
    for (int e = tid * 4; e < 32 * HDIM; e += 32 * 4) {
        int j = e >> 6, d = e & 63;
        *(float4*)&Ks[e] = *(const float4*)(K + (size_t)j * (3*DIM) + d);
        *(float4*)&Vs[e] = *(const float4*)(V + (size_t)j * (3*DIM) + d);
    }
    __syncthreads();

    float q[HDIM];
    const float* qp = Q + (size_t)tid * (3*DIM);
#pragma unroll
    for (int d = 0; d < HDIM; ++d) q[d] = qp[d] * 0.125f;

    float s[32], mx = -1e30f;
#pragma unroll 1
    for (int j = 0; j < 32; ++j) {
        float tt = 0.f;
#pragma unroll
        for (int d = 0; d < HDIM; ++d) tt += q[d] * Ks[j*HDIM + d];
        s[j] = tt;
        if (tt > mx) mx = tt;
    }
    float lsum = 0.f;
#pragma unroll
    for (int j = 0; j < 32; ++j) { s[j] = __expf(s[j] - mx); lsum += s[j]; }
    float acc[HDIM];
#pragma unroll
    for (int d = 0; d < HDIM; ++d) acc[d] = 0.f;
#pragma unroll 1
    for (int j = 0; j < 32; ++j) {
        float p = s[j];
#pragma unroll
        for (int d = 0; d < HDIM; ++d) acc[d] += p * Vs[j*HDIM + d];
    }
    float inv = 1.f / lsum;
    float* op = O + (size_t)(b * 32 + tid) * DIM + (size_t)h * HDIM;
#pragma unroll
    for (int d = 0; d < HDIM; ++d) op[d] = acc[d] * inv;
}

// ---------------- cluster mean ----------------
__global__ void cluster_mean(const float* __restrict__ X, float* __restrict__ R)
{
    const int bc = blockIdx.x;
    const float* xp = X + (size_t)bc * 64 * DIM;
    for (int d = threadIdx.x; d < DIM; d += blockDim.x) {
        float sum = 0.f;
        for (int t = 0; t < 64; ++t) sum += xp[(size_t)t * DIM + d];
        R[(size_t)bc * DIM + d] = sum * (1.f / 64.f);
    }
}

// ---------------- mlp_in = reps_sum(batch) - reps ----------------
__global__ void cluster_diff(const float* __restrict__ R, float* __restrict__ Mi)
{
    const int b = blockIdx.x;
    const int d = threadIdx.x;
    float sum = 0.f;
    for (int c = 0; c < 32; ++c) sum += R[(size_t)(b*32 + c) * DIM + d];
    for (int c = 0; c < 32; ++c)
        Mi[(size_t)(b*32 + c) * DIM + d] = sum - R[(size_t)(b*32 + c) * DIM + d];
}

// ---------------- host ----------------
static void* symp(const void* symbol) {
    void* p = nullptr;
    cudaGetSymbolAddress(&p, symbol);
    return p;
}

extern "C" void kernel_launch(void* const* d_in, const int* in_sizes, int n_in,
                              void* d_out, int out_size)
{
    const float* x   = (const float*)d_in[0];
    const float* lqw = (const float*)d_in[1];
    const float* lqb = (const float*)d_in[2];
    const float* lkw = (const float*)d_in[3];
    const float* lkb = (const float*)d_in[4];
    const float* lvw = (const float*)d_in[5];
    const float* lvb = (const float*)d_in[6];
    const float* low = (const float*)d_in[7];
    const float* lob = (const float*)d_in[8];
    const float* m1w = (const float*)d_in[9];
    const float* m1b = (const float*)d_in[10];
    const float* m2w = (const float*)d_in[11];
    const float* m2b = (const float*)d_in[12];
    const float* gqw = (const float*)d_in[13];
    const float* gqb = (const float*)d_in[14];
    const float* gkw = (const float*)d_in[15];
    const float* gkb = (const float*)d_in[16];
    const float* gvw = (const float*)d_in[17];
    const float* gvb = (const float*)d_in[18];
    const float* gow = (const float*)d_in[19];
    const float* gob = (const float*)d_in[20];
    const float* g1w = (const float*)d_in[21];
    const float* g1b = (const float*)d_in[22];
    const float* g2w = (const float*)d_in[23];
    const float* g2b = (const float*)d_in[24];
    float* out = (float*)d_out;

    float* h1    = (float*)symp(g_h1);
    float* h2    = (float*)symp(g_h2);
    float* reps  = (float*)symp(s_reps);
    float* mlpin = (float*)symp(s_mlpin);
    float* t1    = (float*)symp(s_t1);
    float* mix   = (float*)symp(s_mix);
    float* rqkv  = (float*)symp(s_rqkv);
    float* ratt  = (float*)symp(s_ratt);
    float* rnew  = (float*)symp(s_rnew);
    float* gproj = (float*)symp(s_gproj);
    float* gqkvw = (float*)symp(w_gqkv);
    float* gqkvb = (float*)symp(b_gqkv);
    float* qkvb  = (float*)symp(b_qkv);

    __half* hqkv = (__half*)symp(w_qkv);
    __half* hlo  = (__half*)symp(w_lo);
    __half* hg1  = (__half*)symp(w_g1);
    __half* hg2  = (__half*)symp(w_g2);
    __half* xh   = (__half*)symp(a_x);
    __half* qkvh = (__half*)symp(a_qkv);
    __half* atth = (__half*)symp(a_att);
    __half* h1h  = (__half*)symp(a_h1);
    __half* h2h  = (__half*)symp(a_h2);
    __half* hidh = (__half*)symp(a_hid);

    auto gemm_plain = gemm_h<false>;
    auto gemm_merge = gemm_h<true>;
    cudaFuncSetAttribute(gemm_plain, cudaFuncAttributeMaxDynamicSharedMemorySize, GEMM_H_SMEM);
    cudaFuncSetAttribute(gemm_merge, cudaFuncAttributeMaxDynamicSharedMemorySize, GEMM_H_SMEM);
    auto gemm_sm = gemm_mma<64,64,32,16,2>;
    cudaFuncSetAttribute(gemm_sm, cudaFuncAttributeMaxDynamicSharedMemorySize, GEMM_SMEM_SM);

    // ---- conversions + packs (two launches) ----
    {
        CvtArgs ca;
        ca.src[0] = x;        ca.dst[0] = xh;          ca.n[0] = TOKENS*DIM;
        ca.src[1] = lqw;      ca.dst[1] = hqkv;        ca.n[1] = (int)DD;
        ca.src[2] = lkw;      ca.dst[2] = hqkv + DD;   ca.n[2] = (int)DD;
        ca.src[3] = lvw;      ca.dst[3] = hqkv + 2*DD; ca.n[3] = (int)DD;
        ca.src[4] = lqw + DD; ca.dst[4] = hqkv + 3*DD; ca.n[4] = (int)DD;
        ca.src[5] = lkw + DD; ca.dst[5] = hqkv + 4*DD; ca.n[5] = (int)DD;
        ca.src[6] = lvw + DD; ca.dst[6] = hqkv + 5*DD; ca.n[6] = (int)DD;
        ca.src[7] = low;      ca.dst[7] = hlo;         ca.n[7] = (int)(2*DD);
        ca.src[8] = g1w;      ca.dst[8] = hg1;         ca.n[8] = (int)(2*DD);
        ca.src[9] = g2w;      ca.dst[9] = hg2;         ca.n[9] = (int)DD;
        f2h_kernel<<<dim3(256, 10), 256>>>(ca);
    }
    {
        PackArgs pa;
        pa.src[0] = gqw;         pa.dst[0] = gqkvw;         pa.n[0] = (int)DD;
        pa.src[1] = gkw;         pa.dst[1] = gqkvw + DD;    pa.n[1] = (int)DD;
        pa.src[2] = gvw;         pa.dst[2] = gqkvw + 2*DD;  pa.n[2] = (int)DD;
        pa.src[3] = gqb;         pa.dst[3] = gqkvb;         pa.n[3] = DIM;
        pa.src[4] = gkb;         pa.dst[4] = gqkvb + DIM;   pa.n[4] = DIM;
        pa.src[5] = gvb;         pa.dst[5] = gqkvb + 2*DIM; pa.n[5] = DIM;
        pa.src[6] = lqb;         pa.dst[6] = qkvb;          pa.n[6] = DIM;
        pa.src[7] = lkb;         pa.dst[7] = qkvb + DIM;    pa.n[7] = DIM;
        pa.src[8] = lvb;         pa.dst[8] = qkvb + 2*DIM;  pa.n[8] = DIM;
        pa.src[9] = lqb + DIM;   pa.dst[9] = qkvb + 3*DIM;  pa.n[9] = DIM;
        pa.src[10]= lkb + DIM;   pa.dst[10]= qkvb + 4*DIM;  pa.n[10]= DIM;
        pa.src[11]= lvb + DIM;   pa.dst[11]= qkvb + 5*DIM;  pa.n[11]= DIM;
        packf_kernel<<<dim3(64, 12), 256>>>(pa);
    }

    const dim3 gQKV(3*DIM/128, TOKENS/128);   // 24 x 32
    const dim3 gBig(DIM/128, TOKENS/128);     // 8 x 32
    const dim3 gSm (DIM/64, 1);               // 16 x 1
    const dim3 gSm3(3*DIM/64, 1);             // 48 x 1
    const dim3 gAtt(SEQ/128, HEADS, BATCH);   // 16 x 16 x 2
    const dim3 gCAtt(HEADS, BATCH);

    // ---- local layer 0 ----
    gemm_plain<<<gQKV, 256, GEMM_H_SMEM>>>(xh, hqkv, DIM, qkvb, nullptr, 1, 0, nullptr, qkvh, TOKENS, 3*DIM, DIM, 0, nullptr);
    flash_attn_h<<<gAtt, 256>>>(qkvh, 3*DIM, atth);
    gemm_plain<<<gBig, 256, GEMM_H_SMEM>>>(atth, hlo, DIM, lob, x, 1, DIM, h1, h1h, TOKENS, DIM, DIM, 0, nullptr);

    // ---- local layer 1 ----
    gemm_plain<<<gQKV, 256, GEMM_H_SMEM>>>(h1h, hqkv + 3*DD, DIM, qkvb + 3*DIM, nullptr, 1, 0, nullptr, qkvh, TOKENS, 3*DIM, DIM, 0, nullptr);
    flash_attn_h<<<gAtt, 256>>>(qkvh, 3*DIM, atth);
    gemm_plain<<<gBig, 256, GEMM_H_SMEM>>>(atth, hlo + DD, DIM, lob + DIM, h1, 1, DIM, h2, h2h, TOKENS, DIM, DIM, 0, nullptr);
    // h2 = x_local (fp32) / h2h (fp16)

    // ---- cluster path ----
    cluster_mean<<<NCLUST, 256>>>(h2, reps);
    cluster_diff<<<BATCH, DIM>>>(reps, mlpin);
    gemm_sm<<<gSm, 256, GEMM_SMEM_SM>>>(mlpin, m1w, DIM, m1b, nullptr, 1, t1, NCLUST, DIM, DIM, 1);
    gemm_sm<<<gSm, 256, GEMM_SMEM_SM>>>(t1, m2w, DIM, m2b, reps, 1, mix, NCLUST, DIM, DIM, 0);
    gemm_sm<<<gSm3, 256, GEMM_SMEM_SM>>>(mix, gqkvw, DIM, gqkvb, nullptr, 1, rqkv, NCLUST, 3*DIM, DIM, 0);
    cluster_attn<<<gCAtt, 32>>>(rqkv, ratt);
    gemm_sm<<<gSm, 256, GEMM_SMEM_SM>>>(ratt, gow, DIM, gob, nullptr, 1, rnew, NCLUST, DIM, DIM, 0);

    // gproj = reps_new @ W1b^T (second half of g1w columns, ldb = 2*DIM)
    gemm_sm<<<gSm, 256, GEMM_SMEM_SM>>>(rnew, g1w + DIM, 2*DIM, nullptr, nullptr, 1, gproj, NCLUST, DIM, DIM, 0);

    // hidden = gelu(x_local @ W1a^T + g1b + broadcast(gproj))
    gemm_plain<<<gBig, 256, GEMM_H_SMEM>>>(h2h, hg1, 2*DIM, g1b, gproj, 64, DIM, nullptr, hidh, TOKENS, DIM, DIM, 1, nullptr);
    // out = x_local + sigmoid(hidden @ g2w^T + g2b) * (broadcast(rnew) - x_local)   [fused, dedicated kernel]
    gemm_merge<<<gBig, 256, GEMM_H_SMEM>>>(hidh, hg2, DIM, g2b, rnew, 64, DIM, out, nullptr, TOKENS, DIM, DIM, 3, h2);
}

// round 17
// speedup vs baseline: 1.0201x; 1.0135x over previous
#include <cuda_runtime.h>
#include <cuda_fp16.h>
#include <math.h>
#include <stdint.h>

#define BATCH 2
#define SEQ   2048
#define DIM   1024
#define HEADS 16
#define HDIM  64
#define TOKENS (BATCH*SEQ)        /* 4096 */
#define NCLUST 64                 /* B*C = 2*32 */
#define DD ((size_t)DIM*DIM)

// ---------------- scratch (static device arrays; no allocations) ----------------
__device__ float g_h1 [(size_t)TOKENS*DIM];
__device__ float g_h2 [(size_t)TOKENS*DIM];

__device__ float s_reps [NCLUST*DIM];
__device__ float s_mlpin[NCLUST*DIM];
__device__ float s_t1   [NCLUST*DIM];
__device__ float s_mix  [NCLUST*DIM];
__device__ float s_rqkv [NCLUST*3*DIM];
__device__ float s_ratt [NCLUST*DIM];
__device__ float s_rnew [NCLUST*DIM];
__device__ float s_gproj[NCLUST*DIM];

__device__ float w_gqkv[3*DD];
__device__ float b_gqkv[3*DIM];
__device__ float b_qkv [2*3*DIM];

// fp16 buffers
__device__ __half w_qkv[6*DD];
__device__ __half w_lo[2*DD];
__device__ __half w_g1[2*DD];
__device__ __half w_g2[DD];
__device__ __half a_x   [(size_t)TOKENS*DIM];
__device__ __half a_qkv [(size_t)TOKENS*3*DIM];
__device__ __half a_att [(size_t)TOKENS*DIM];
__device__ __half a_h1  [(size_t)TOKENS*DIM];
__device__ __half a_h2  [(size_t)TOKENS*DIM];
__device__ __half a_hid [(size_t)TOKENS*DIM];

// ---------------- PTX helpers ----------------
__device__ __forceinline__ uint32_t smem_u32(const void* p) {
    uint32_t a;
    asm("{ .reg .u64 t; cvta.to.shared.u64 t, %1; cvt.u32.u64 %0, t; }" : "=r"(a) : "l"(p));
    return a;
}
__device__ __forceinline__ void cpa16(uint32_t saddr, const void* g) {
    asm volatile("cp.async.cg.shared.global [%0], [%1], 16;" :: "r"(saddr), "l"(g));
}
#define CP_COMMIT() asm volatile("cp.async.commit_group;" ::: "memory")
template<int N>
__device__ __forceinline__ void cp_wait() {
    asm volatile("cp.async.wait_group %0;" :: "n"(N) : "memory");
}
__device__ __forceinline__ uint32_t cvt_tf32(float v) {
    uint32_t r;
    asm("cvt.rna.tf32.f32 %0, %1;" : "=r"(r) : "f"(v));
    return r;
}
__device__ __forceinline__ void mma8(float* c, const uint32_t* a, const uint32_t* b) {
    asm volatile(
        "mma.sync.aligned.m16n8k8.row.col.f32.tf32.tf32.f32 "
        "{%0,%1,%2,%3}, {%4,%5,%6,%7}, {%8,%9}, {%0,%1,%2,%3};"
        : "+f"(c[0]), "+f"(c[1]), "+f"(c[2]), "+f"(c[3])
        : "r"(a[0]), "r"(a[1]), "r"(a[2]), "r"(a[3]), "r"(b[0]), "r"(b[1]));
}
__device__ __forceinline__ void mma16h(float* c, const uint32_t* a, const uint32_t* b) {
    asm volatile(
        "mma.sync.aligned.m16n8k16.row.col.f32.f16.f16.f32 "
        "{%0,%1,%2,%3}, {%4,%5,%6,%7}, {%8,%9}, {%0,%1,%2,%3};"
        : "+f"(c[0]), "+f"(c[1]), "+f"(c[2]), "+f"(c[3])
        : "r"(a[0]), "r"(a[1]), "r"(a[2]), "r"(a[3]), "r"(b[0]), "r"(b[1]));
}
__device__ __forceinline__ void ldsm4(uint32_t* r, uint32_t saddr) {
    asm volatile("ldmatrix.sync.aligned.m8n8.x4.shared.b16 {%0,%1,%2,%3}, [%4];"
        : "=r"(r[0]), "=r"(r[1]), "=r"(r[2]), "=r"(r[3]) : "r"(saddr));
}
__device__ __forceinline__ void ldsm4t(uint32_t* r, uint32_t saddr) {
    asm volatile("ldmatrix.sync.aligned.m8n8.x4.trans.shared.b16 {%0,%1,%2,%3}, [%4];"
        : "=r"(r[0]), "=r"(r[1]), "=r"(r[2]), "=r"(r[3]) : "r"(saddr));
}
__device__ __forceinline__ uint32_t packh2(float a, float b) {
    __half2 h = __floats2half2_rn(a, b);
    return *(uint32_t*)&h;
}

// ---------------- epilogue (act: 0 none, 1 gelu, 2 sigmoid) ----------------
__device__ __forceinline__ float epilogue(float v, int m, int n,
                                          const float* __restrict__ bias,
                                          const float* __restrict__ add, int addDiv,
                                          int addLd, int act) {
    if (bias) v += bias[n];
    if (add)  v += add[(size_t)(m / addDiv) * addLd + n];
    if (act == 1) {
        v = 0.5f * v * (1.0f + erff(v * 0.70710678118654752f));
    } else if (act == 2) {
        v = 1.0f / (1.0f + expf(-v));
    }
    return v;
}

// ---------------- fp32 -> fp16 bulk conversion (single launch, 10 segments) ----------------
struct CvtArgs {
    const float* src[10];
    __half* dst[10];
    int n[10];
};
__global__ void f2h_kernel(CvtArgs args) {
    const int seg = blockIdx.y;
    const int n4 = args.n[seg] >> 2;
    const float4* s = (const float4*)args.src[seg];
    __half2* d = (__half2*)args.dst[seg];
    for (int i = blockIdx.x * blockDim.x + threadIdx.x; i < n4; i += gridDim.x * blockDim.x) {
        float4 v = s[i];
        d[2*i]   = __floats2half2_rn(v.x, v.y);
        d[2*i+1] = __floats2half2_rn(v.z, v.w);
    }
}

// ---------------- fp32 pack copies (single launch, 12 segments) ----------------
struct PackArgs {
    const float* src[12];
    float* dst[12];
    int n[12];
};
__global__ void packf_kernel(PackArgs args) {
    const int seg = blockIdx.y;
    const int n4 = args.n[seg] >> 2;
    const float4* s = (const float4*)args.src[seg];
    float4* d = (float4*)args.dst[seg];
    for (int i = blockIdx.x * blockDim.x + threadIdx.x; i < n4; i += gridDim.x * blockDim.x)
        d[i] = s[i];
}

// ---------------- fp16 mma GEMM: C[M,N] = A[M,K] * B[N,K]^T (+bias,+add,act) ----------------
// 128x128 CTA tile, 8 warps (2x4), warp tile 64x32, BK=32, 4-stage cp.async. (R9/R11 proven)
// MERGE=true: final-gate variant — C = XL + sigmoid(v+bias) * (add_bcast - XL).
#define HPITCH 40
#define HSTAGES 4
#define GEMM_H_SMEM (HSTAGES * 2 * 128 * HPITCH * 2)   /* 81920 */

template<bool MERGE>
__global__ __launch_bounds__(256, 2)
void gemm_h(const __half* __restrict__ A,
            const __half* __restrict__ B, int ldb,
            const float* __restrict__ bias,
            const float* __restrict__ add, int addDiv, int addLd,
            float* __restrict__ C, __half* __restrict__ Ch,
            int M, int Nn, int K, int act,
            const float* __restrict__ XL)
{
    extern __shared__ __half hsm[];
    __half* Asm = hsm;
    __half* Bsm = hsm + HSTAGES * 128 * HPITCH;

    const int tid  = threadIdx.x;
    const int wid  = tid >> 5;
    const int lane = tid & 31;
    const int warp_m = wid >> 2;     // 0..1
    const int warp_n = wid & 3;      // 0..3
    const int m0 = blockIdx.y * 128;
    const int n0 = blockIdx.x * 128;
    const int g = lane >> 2;
    const int t = lane & 3;

    const uint32_t a_loff = ((uint32_t)(lane & 15) * HPITCH + (uint32_t)(lane >> 4) * 8) * 2;
    const uint32_t b_row  = (uint32_t)(lane & 7) + (uint32_t)((lane >> 1) & 8);
    const uint32_t b_loff = (b_row * HPITCH + (uint32_t)(lane & 8)) * 2;

    float acc[4][4][4];
#pragma unroll
    for (int mi = 0; mi < 4; ++mi)
#pragma unroll
        for (int ni = 0; ni < 4; ++ni)
#pragma unroll
            for (int r = 0; r < 4; ++r) acc[mi][ni][r] = 0.f;

    auto load = [&](int kc, int s) {
        const int k0 = kc * 32;
        __half* da = Asm + s * 128 * HPITCH;
        __half* db = Bsm + s * 128 * HPITCH;
#pragma unroll
        for (int f = tid; f < 512; f += 256) {
            int r = f >> 2, c = f & 3;
            int am = m0 + r; if (am > M - 1) am = M - 1;
            cpa16(smem_u32(da + r * HPITCH + c * 8), A + (size_t)am * K + k0 + c * 8);
        }
#pragma unroll
        for (int f = tid; f < 512; f += 256) {
            int r = f >> 2, c = f & 3;
            cpa16(smem_u32(db + r * HPITCH + c * 8), B + (size_t)(n0 + r) * ldb + k0 + c * 8);
        }
    };

    auto compute = [&](int s) {
        const uint32_t abase = smem_u32(Asm + s * 128 * HPITCH + warp_m * 64 * HPITCH) + a_loff;
        const uint32_t bbase = smem_u32(Bsm + s * 128 * HPITCH + warp_n * 32 * HPITCH) + b_loff;
#pragma unroll
        for (int ks = 0; ks < 2; ++ks) {
            uint32_t af[4][4], bf[4][2];
#pragma unroll
            for (int mi = 0; mi < 4; ++mi)
                ldsm4(af[mi], abase + (uint32_t)(mi * 16 * HPITCH + ks * 16) * 2);
#pragma unroll
            for (int p = 0; p < 2; ++p) {
                uint32_t r[4];
                ldsm4(r, bbase + (uint32_t)(p * 16 * HPITCH + ks * 16) * 2);
                bf[2*p][0] = r[0]; bf[2*p][1] = r[1];
                bf[2*p+1][0] = r[2]; bf[2*p+1][1] = r[3];
            }
#pragma unroll
            for (int mi = 0; mi < 4; ++mi)
#pragma unroll
                for (int ni = 0; ni < 4; ++ni)
                    mma16h(acc[mi][ni], af[mi], bf[ni]);
        }
    };

    const int NC = K >> 5;
#pragma unroll
    for (int s = 0; s < HSTAGES - 1; ++s) {
        if (s < NC) load(s, s);
        CP_COMMIT();
    }
    for (int kc = 0; kc < NC; ++kc) {
        if (kc + HSTAGES - 1 < NC) {
            load(kc + HSTAGES - 1, (kc + HSTAGES - 1) & (HSTAGES - 1));
            CP_COMMIT();
            cp_wait<HSTAGES - 1>();
        } else {
            cp_wait<0>();
        }
        __syncthreads();
        compute(kc & (HSTAGES - 1));
        __syncthreads();
    }

#pragma unroll
    for (int mi = 0; mi < 4; ++mi) {
#pragma unroll
        for (int ni = 0; ni < 4; ++ni) {
            int row = m0 + warp_m * 64 + mi * 16 + g;
            int col = n0 + warp_n * 32 + ni * 8 + 2 * t;
#pragma unroll
            for (int half_ = 0; half_ < 2; ++half_) {
                int rr = row + half_ * 8;
                if (rr >= M) continue;
                if (MERGE) {
                    float2 o;
#pragma unroll
                    for (int e = 0; e < 2; ++e) {
                        float v = acc[mi][ni][half_*2 + e] + bias[col + e];
                        float sx = 1.f / (1.f + expf(-v));
                        float xl = XL[(size_t)rr * Nn + col + e];
                        float xg = add[(size_t)(rr / addDiv) * addLd + col + e];
                        ((float*)&o)[e] = xl + sx * (xg - xl);
                    }
                    *(float2*)&C[(size_t)rr * Nn + col] = o;
                } else {
                    float vx = epilogue(acc[mi][ni][half_*2],   rr, col,     bias, add, addDiv, addLd, act);
                    float vy = epilogue(acc[mi][ni][half_*2+1], rr, col + 1, bias, add, addDiv, addLd, act);
                    if (C)  *(float2*)&C[(size_t)rr * Nn + col] = make_float2(vx, vy);
                    if (Ch) *(__half2*)&Ch[(size_t)rr * Nn + col] = __floats2half2_rn(vx, vy);
                }
            }
        }
    }
}

// ---------------- tf32 mma.sync GEMM (small cluster chain), BK=64, 2 stages (R11 proven) ----------------
#define SPITCH 68

template<int BM, int BN, int WM, int WN, int NSTAGE>
__global__ __launch_bounds__(256, 3)
void gemm_mma(const float* __restrict__ A,
              const float* __restrict__ B, int ldb,
              const float* __restrict__ bias,
              const float* __restrict__ add, int addDiv,
              float* __restrict__ C, int M, int Nn, int K, int act)
{
    constexpr int MI  = WM / 16;
    constexpr int NI  = WN / 8;
    constexpr int WGN = BN / WN;

    extern __shared__ float sm[];
    float* Asm = sm;
    float* Bsm = sm + NSTAGE * BM * SPITCH;

    const int tid  = threadIdx.x;
    const int wid  = tid >> 5;
    const int lane = tid & 31;
    const int warp_m = wid / WGN;
    const int warp_n = wid % WGN;
    const int m0 = blockIdx.y * BM;
    const int n0 = blockIdx.x * BN;
    const int g = lane >> 2;
    const int t = lane & 3;

    float acc[MI][NI][4];
#pragma unroll
    for (int mi = 0; mi < MI; ++mi)
#pragma unroll
        for (int ni = 0; ni < NI; ++ni)
#pragma unroll
            for (int r = 0; r < 4; ++r) acc[mi][ni][r] = 0.f;

    auto load = [&](int kc, int s) {
        const int k0 = kc * 64;
        float* da = Asm + s * BM * SPITCH;
        float* db = Bsm + s * BN * SPITCH;
#pragma unroll
        for (int f = tid; f < BM * 16; f += 256) {
            int r = f >> 4, c4 = f & 15;
            int am = m0 + r; if (am > M - 1) am = M - 1;
            cpa16(smem_u32(da + r * SPITCH + c4 * 4), A + (size_t)am * K + k0 + c4 * 4);
        }
#pragma unroll
        for (int f = tid; f < BN * 16; f += 256) {
            int r = f >> 4, c4 = f & 15;
            cpa16(smem_u32(db + r * SPITCH + c4 * 4), B + (size_t)(n0 + r) * ldb + k0 + c4 * 4);
        }
    };

    auto compute = [&](int s) {
        const float* da = Asm + s * BM * SPITCH + (size_t)warp_m * WM * SPITCH;
        const float* db = Bsm + s * BN * SPITCH + (size_t)warp_n * WN * SPITCH;
#pragma unroll
        for (int ks = 0; ks < 8; ++ks) {
            uint32_t af[MI][4], bf[NI][2];
#pragma unroll
            for (int mi = 0; mi < MI; ++mi) {
                const float* p = da + (mi * 16 + g) * SPITCH + ks * 8 + t;
                af[mi][0] = cvt_tf32(p[0]);
                af[mi][1] = cvt_tf32(p[8 * SPITCH]);
                af[mi][2] = cvt_tf32(p[4]);
                af[mi][3] = cvt_tf32(p[8 * SPITCH + 4]);
            }
#pragma unroll
            for (int ni = 0; ni < NI; ++ni) {
                const float* p = db + (ni * 8 + g) * SPITCH + ks * 8 + t;
                bf[ni][0] = cvt_tf32(p[0]);
                bf[ni][1] = cvt_tf32(p[4]);
            }
#pragma unroll
            for (int mi = 0; mi < MI; ++mi)
#pragma unroll
                for (int ni = 0; ni < NI; ++ni)
                    mma8(acc[mi][ni], af[mi], bf[ni]);
        }
    };

    const int NC = K >> 6;
#pragma unroll
    for (int s = 0; s < NSTAGE - 1; ++s) {
        if (s < NC) load(s, s);
        CP_COMMIT();
    }
    for (int kc = 0; kc < NC; ++kc) {
        if (kc + NSTAGE - 1 < NC) {
            load(kc + NSTAGE - 1, (kc + NSTAGE - 1) % NSTAGE);
            CP_COMMIT();
            cp_wait<NSTAGE - 1>();
        } else {
            cp_wait<0>();
        }
        __syncthreads();
        compute(kc % NSTAGE);
        __syncthreads();
    }

#pragma unroll
    for (int mi = 0; mi < MI; ++mi) {
#pragma unroll
        for (int ni = 0; ni < NI; ++ni) {
            int row = m0 + warp_m * WM + mi * 16 + g;
            int col = n0 + warp_n * WN + ni * 8 + 2 * t;
            if (row < M) {
                float2 v0;
                v0.x = epilogue(acc[mi][ni][0], row, col,     bias, add, addDiv, Nn, act);
                v0.y = epilogue(acc[mi][ni][1], row, col + 1, bias, add, addDiv, Nn, act);
                *(float2*)&C[(size_t)row * Nn + col] = v0;
            }
            if (row + 8 < M) {
                float2 v1;
                v1.x = epilogue(acc[mi][ni][2], row + 8, col,     bias, add, addDiv, Nn, act);
                v1.y = epilogue(acc[mi][ni][3], row + 8, col + 1, bias, add, addDiv, Nn, act);
                *(float2*)&C[(size_t)(row + 8) * Nn + col] = v1;
            }
        }
    }
}

#define GEMM_SMEM_SM  (2*(64+64)*SPITCH*4)    /* 69632 */

// ---------------- flash attention (windowed causal), full fp16 mma (R14 proven, occ 4) ----------------
#define FPITCH 72

__global__ __launch_bounds__(128, 4)
void flash_attn_h(const __half* __restrict__ QKV, int ldq, __half* __restrict__ Oh)
{
    const int i0 = blockIdx.x * 64;
    const int h = blockIdx.y, b = blockIdx.z;
    const size_t hb = (size_t)b * SEQ * ldq + (size_t)h * HDIM;
    const size_t ho = (size_t)b * SEQ * DIM + (size_t)h * HDIM;
    const __half* Q = QKV + hb;
    const __half* K = QKV + hb + DIM;
    const __half* V = QKV + hb + 2 * DIM;
    const int tid = threadIdx.x;
    const int wid = tid >> 5;
    const int lane = tid & 31;
    const int g = lane >> 2;
    const int t = lane & 3;

    __shared__ __align__(16) __half Ks[2][64 * FPITCH];
    __shared__ __align__(16) __half Vs[2][64 * FPITCH];

    for (int e = tid; e < 512; e += 128) {
        int r = e >> 3, c8 = (e & 7) * 8;
        *(float4*)&Ks[0][r * FPITCH + c8] = *(const float4*)(Q + (size_t)(i0 + r) * ldq + c8);
    }
    __syncthreads();
    uint32_t qf[4][4];
    {
        const uint32_t qb = smem_u32(&Ks[0][(wid * 16) * FPITCH]) +
            (((uint32_t)(lane & 15) * FPITCH + (uint32_t)(lane >> 4) * 8) * 2);
#pragma unroll
        for (int ks = 0; ks < 4; ++ks)
            ldsm4(qf[ks], qb + (uint32_t)(ks * 16) * 2);
    }
    __syncthreads();

    float of[8][4];
#pragma unroll
    for (int nt = 0; nt < 8; ++nt)
#pragma unroll
        for (int r = 0; r < 4; ++r) of[nt][r] = 0.f;
    float m0 = -1e30f, m1 = -1e30f, l0 = 0.f, l1 = 0.f;

    const int rowA = i0 + wid * 16 + g;
    const int rowB = rowA + 8;
    const int c0 = (i0 >= 256) ? (i0 - 256) : 0;
    const uint32_t k_loff = (((uint32_t)((lane & 7) + ((lane >> 1) & 8)) * FPITCH + (uint32_t)(lane & 8)) * 2);

    auto loadKV = [&](int c, int s) {
#pragma unroll
        for (int f = tid; f < 512; f += 128) {
            int r = f >> 3, c8 = (f & 7) * 8;
            cpa16(smem_u32(&Ks[s][r * FPITCH + c8]), K + (size_t)(c + r) * ldq + c8);
            cpa16(smem_u32(&Vs[s][r * FPITCH + c8]), V + (size_t)(c + r) * ldq + c8);
        }
    };

    loadKV(c0, 0);
    CP_COMMIT();

    const int nch = (i0 - c0) / 64 + 1;
    for (int i = 0; i < nch; ++i) {
        const int c = c0 + i * 64;
        const int st = i & 1;
        if (i + 1 < nch) {
            loadKV(c + 64, st ^ 1);
            CP_COMMIT();
            cp_wait<1>();
        } else {
            cp_wait<0>();
        }
        __syncthreads();

        const uint32_t kb = smem_u32(Ks[st]) + k_loff;
        const uint32_t vb = smem_u32(Vs[st]) + lane * (FPITCH * 2);

        float sc[8][4];
#pragma unroll
        for (int nt = 0; nt < 8; ++nt)
#pragma unroll
            for (int r = 0; r < 4; ++r) sc[nt][r] = 0.f;
#pragma unroll
        for (int ks = 0; ks < 4; ++ks) {
#pragma unroll
            for (int p = 0; p < 4; ++p) {
                uint32_t r[4];
                ldsm4(r, kb + (uint32_t)(p * 16 * FPITCH + ks * 16) * 2);
                mma16h(sc[2*p],   qf[ks], r);
                mma16h(sc[2*p+1], qf[ks], r + 2);
            }
        }

#pragma unroll
        for (int nt = 0; nt < 8; ++nt)
#pragma unroll
            for (int r = 0; r < 4; ++r) sc[nt][r] *= 0.125f;

        const bool mlo = (i0 >= 256) && (c == c0);
        const bool mhi = (c == i0);
        if (mlo | mhi) {
#pragma unroll
            for (int nt = 0; nt < 8; ++nt) {
                int col = c + nt * 8 + 2 * t;
#pragma unroll
                for (int e = 0; e < 2; ++e) {
                    int j = col + e;
                    if ((mhi && j > rowA) || (mlo && j < rowA - 256)) sc[nt][e]     = -1e30f;
                    if ((mhi && j > rowB) || (mlo && j < rowB - 256)) sc[nt][e + 2] = -1e30f;
                }
            }
        }

        float mxA = -1e30f, mxB = -1e30f;
#pragma unroll
        for (int nt = 0; nt < 8; ++nt) {
            mxA = fmaxf(mxA, fmaxf(sc[nt][0], sc[nt][1]));
            mxB = fmaxf(mxB, fmaxf(sc[nt][2], sc[nt][3]));
        }
        mxA = fmaxf(mxA, __shfl_xor_sync(0xffffffffu, mxA, 1));
        mxA = fmaxf(mxA, __shfl_xor_sync(0xffffffffu, mxA, 2));
        mxB = fmaxf(mxB, __shfl_xor_sync(0xffffffffu, mxB, 1));
        mxB = fmaxf(mxB, __shfl_xor_sync(0xffffffffu, mxB, 2));
        float nm0 = fmaxf(m0, mxA), nm1 = fmaxf(m1, mxB);
        float e0 = __expf(m0 - nm0), e1 = __expf(m1 - nm1);
        float sA = 0.f, sB = 0.f;
#pragma unroll
        for (int nt = 0; nt < 8; ++nt) {
            sc[nt][0] = __expf(sc[nt][0] - nm0);
            sc[nt][1] = __expf(sc[nt][1] - nm0);
            sc[nt][2] = __expf(sc[nt][2] - nm1);
            sc[nt][3] = __expf(sc[nt][3] - nm1);
            sA += sc[nt][0] + sc[nt][1];
            sB += sc[nt][2] + sc[nt][3];
        }
        sA += __shfl_xor_sync(0xffffffffu, sA, 1);
        sA += __shfl_xor_sync(0xffffffffu, sA, 2);
        sB += __shfl_xor_sync(0xffffffffu, sB, 1);
        sB += __shfl_xor_sync(0xffffffffu, sB, 2);
        l0 = l0 * e0 + sA;
        l1 = l1 * e1 + sB;
        m0 = nm0; m1 = nm1;
#pragma unroll
        for (int nt = 0; nt < 8; ++nt) {
            of[nt][0] *= e0; of[nt][1] *= e0;
            of[nt][2] *= e1; of[nt][3] *= e1;
        }

        uint32_t af[4][4];
#pragma unroll
        for (int kg = 0; kg < 4; ++kg) {
            af[kg][0] = packh2(sc[2*kg][0],   sc[2*kg][1]);
            af[kg][1] = packh2(sc[2*kg][2],   sc[2*kg][3]);
            af[kg][2] = packh2(sc[2*kg+1][0], sc[2*kg+1][1]);
            af[kg][3] = packh2(sc[2*kg+1][2], sc[2*kg+1][3]);
        }

#pragma unroll
        for (int nt = 0; nt < 8; ++nt) {
            uint32_t vf[8];
            ldsm4t(vf,     vb + nt * 16);
            ldsm4t(vf + 4, vb + 32 * (FPITCH * 2) + nt * 16);
            mma16h(of[nt], af[0], vf);
            mma16h(of[nt], af[1], vf + 2);
            mma16h(of[nt], af[2], vf + 4);
            mma16h(of[nt], af[3], vf + 6);
        }
        __syncthreads();
    }

    float r0 = 1.f / l0, r1 = 1.f / l1;
#pragma unroll
    for (int nt = 0; nt < 8; ++nt) {
        *(__half2*)(Oh + ho + (size_t)rowA * DIM + nt * 8 + 2 * t) =
            __floats2half2_rn(of[nt][0] * r0, of[nt][1] * r0);
        *(__half2*)(Oh + ho + (size_t)rowB * DIM + nt * 8 + 2 * t) =
            __floats2half2_rn(of[nt][2] * r1, of[nt][3] * r1);
    }
}

// ---------------- global cluster attention (32 tokens per batch) ----------------
__global__ __launch_bounds__(32)
void cluster_attn(const float* __restrict__ QKV, float* __restrict__ O)
{
    const int h = blockIdx.x, b = blockIdx.y;
    const int tid = threadIdx.x;
    const size_t base = (size_t)b * 32 * (3*DIM) + (size_t)h * HDIM;
    const float* Q = QKV + base;
    const float* K = QKV + base + DIM;
    const float* V = QKV + base + 2 * DIM;

    __shared__ __align__(16) float Ks[32*HDIM];
    __shared__ __align__(16) float Vs[32*HDIM];
    for (int e = tid * 4; e < 32 * HDIM; e += 32 * 4) {
        int j = e >> 6, d = e & 63;
        *(float4*)&Ks[e] = *(const float4*)(K + (size_t)j * (3*DIM) + d);
        *(float4*)&Vs[e] = *(const float4*)(V + (size_t)j * (3*DIM) + d);
    }
    __syncthreads();

    float q[HDIM];
    const float* qp = Q + (size_t)tid * (3*DIM);
#pragma unroll
    for (int d = 0; d < HDIM; ++d) q[d] = qp[d] * 0.125f;

    float s[32], mx = -1e30f;
#pragma unroll 1
    for (int j = 0; j < 32; ++j) {
        float tt = 0.f;
#pragma unroll
        for (int d = 0; d < HDIM; ++d) tt += q[d] * Ks[j*HDIM + d];
        s[j] = tt;
        if (tt > mx) mx = tt;
    }
    float lsum = 0.f;
#pragma unroll
    for (int j = 0; j < 32; ++j) { s[j] = __expf(s[j] - mx); lsum += s[j]; }
    float acc[HDIM];
#pragma unroll
    for (int d = 0; d < HDIM; ++d) acc[d] = 0.f;
#pragma unroll 1
    for (int j = 0; j < 32; ++j) {
        float p = s[j];
#pragma unroll
        for (int d = 0; d < HDIM; ++d) acc[d] += p * Vs[j*HDIM + d];
    }
    float inv = 1.f / lsum;
    float* op = O + (size_t)(b * 32 + tid) * DIM + (size_t)h * HDIM;
#pragma unroll
    for (int d = 0; d < HDIM; ++d) op[d] = acc[d] * inv;
}

// ---------------- cluster mean ----------------
__global__ void cluster_mean(const float* __restrict__ X, float* __restrict__ R)
{
    const int bc = blockIdx.x;
    const float* xp = X + (size_t)bc * 64 * DIM;
    for (int d = threadIdx.x; d < DIM; d += blockDim.x) {
        float sum = 0.f;
        for (int t = 0; t < 64; ++t) sum += xp[(size_t)t * DIM + d];
        R[(size_t)bc * DIM + d] = sum * (1.f / 64.f);
    }
}

// ---------------- mlp_in = reps_sum(batch) - reps ----------------
__global__ void cluster_diff(const float* __restrict__ R, float* __restrict__ Mi)
{
    const int b = blockIdx.x;
    const int d = threadIdx.x;
    float sum = 0.f;
    for (int c = 0; c < 32; ++c) sum += R[(size_t)(b*32 + c) * DIM + d];
    for (int c = 0; c < 32; ++c)
        Mi[(size_t)(b*32 + c) * DIM + d] = sum - R[(size_t)(b*32 + c) * DIM + d];
}

// ---------------- host ----------------
static void* symp(const void* symbol) {
    void* p = nullptr;
    cudaGetSymbolAddress(&p, symbol);
    return p;
}

extern "C" void kernel_launch(void* const* d_in, const int* in_sizes, int n_in,
                              void* d_out, int out_size)
{
    const float* x   = (const float*)d_in[0];
    const float* lqw = (const float*)d_in[1];
    const float* lqb = (const float*)d_in[2];
    const float* lkw = (const float*)d_in[3];
    const float* lkb = (const float*)d_in[4];
    const float* lvw = (const float*)d_in[5];
    const float* lvb = (const float*)d_in[6];
    const float* low = (const float*)d_in[7];
    const float* lob = (const float*)d_in[8];
    const float* m1w = (const float*)d_in[9];
    const float* m1b = (const float*)d_in[10];
    const float* m2w = (const float*)d_in[11];
    const float* m2b = (const float*)d_in[12];
    const float* gqw = (const float*)d_in[13];
    const float* gqb = (const float*)d_in[14];
    const float* gkw = (const float*)d_in[15];
    const float* gkb = (const float*)d_in[16];
    const float* gvw = (const float*)d_in[17];
    const float* gvb = (const float*)d_in[18];
    const float* gow = (const float*)d_in[19];
    const float* gob = (const float*)d_in[20];
    const float* g1w = (const float*)d_in[21];
    const float* g1b = (const float*)d_in[22];
    const float* g2w = (const float*)d_in[23];
    const float* g2b = (const float*)d_in[24];
    float* out = (float*)d_out;

    float* h1    = (float*)symp(g_h1);
    float* h2    = (float*)symp(g_h2);
    float* reps  = (float*)symp(s_reps);
    float* mlpin = (float*)symp(s_mlpin);
    float* t1    = (float*)symp(s_t1);
    float* mix   = (float*)symp(s_mix);
    float* rqkv  = (float*)symp(s_rqkv);
    float* ratt  = (float*)symp(s_ratt);
    float* rnew  = (float*)symp(s_rnew);
    float* gproj = (float*)symp(s_gproj);
    float* gqkvw = (float*)symp(w_gqkv);
    float* gqkvb = (float*)symp(b_gqkv);
    float* qkvb  = (float*)symp(b_qkv);

    __half* hqkv = (__half*)symp(w_qkv);
    __half* hlo  = (__half*)symp(w_lo);
    __half* hg1  = (__half*)symp(w_g1);
    __half* hg2  = (__half*)symp(w_g2);
    __half* xh   = (__half*)symp(a_x);
    __half* qkvh = (__half*)symp(a_qkv);
    __half* atth = (__half*)symp(a_att);
    __half* h1h  = (__half*)symp(a_h1);
    __half* h2h  = (__half*)symp(a_h2);
    __half* hidh = (__half*)symp(a_hid);

    auto gemm_plain = gemm_h<false>;
    auto gemm_merge = gemm_h<true>;
    cudaFuncSetAttribute(gemm_plain, cudaFuncAttributeMaxDynamicSharedMemorySize, GEMM_H_SMEM);
    cudaFuncSetAttribute(gemm_merge, cudaFuncAttributeMaxDynamicSharedMemorySize, GEMM_H_SMEM);
    auto gemm_sm = gemm_mma<64,64,32,16,2>;
    cudaFuncSetAttribute(gemm_sm, cudaFuncAttributeMaxDynamicSharedMemorySize, GEMM_SMEM_SM);

    // ---- conversions + packs (two launches) ----
    {
        CvtArgs ca;
        ca.src[0] = x;        ca.dst[0] = xh;          ca.n[0] = TOKENS*DIM;
        ca.src[1] = lqw;      ca.dst[1] = hqkv;        ca.n[1] = (int)DD;
        ca.src[2] = lkw;      ca.dst[2] = hqkv + DD;   ca.n[2] = (int)DD;
        ca.src[3] = lvw;      ca.dst[3] = hqkv + 2*DD; ca.n[3] = (int)DD;
        ca.src[4] = lqw + DD; ca.dst[4] = hqkv + 3*DD; ca.n[4] = (int)DD;
        ca.src[5] = lkw + DD; ca.dst[5] = hqkv + 4*DD; ca.n[5] = (int)DD;
        ca.src[6] = lvw + DD; ca.dst[6] = hqkv + 5*DD; ca.n[6] = (int)DD;
        ca.src[7] = low;      ca.dst[7] = hlo;         ca.n[7] = (int)(2*DD);
        ca.src[8] = g1w;      ca.dst[8] = hg1;         ca.n[8] = (int)(2*DD);
        ca.src[9] = g2w;      ca.dst[9] = hg2;         ca.n[9] = (int)DD;
        f2h_kernel<<<dim3(256, 10), 256>>>(ca);
    }
    {
        PackArgs pa;
        pa.src[0] = gqw;         pa.dst[0] = gqkvw;         pa.n[0] = (int)DD;
        pa.src[1] = gkw;         pa.dst[1] = gqkvw + DD;    pa.n[1] = (int)DD;
        pa.src[2] = gvw;         pa.dst[2] = gqkvw + 2*DD;  pa.n[2] = (int)DD;
        pa.src[3] = gqb;         pa.dst[3] = gqkvb;         pa.n[3] = DIM;
        pa.src[4] = gkb;         pa.dst[4] = gqkvb + DIM;   pa.n[4] = DIM;
        pa.src[5] = gvb;         pa.dst[5] = gqkvb + 2*DIM; pa.n[5] = DIM;
        pa.src[6] = lqb;         pa.dst[6] = qkvb;          pa.n[6] = DIM;
        pa.src[7] = lkb;         pa.dst[7] = qkvb + DIM;    pa.n[7] = DIM;
        pa.src[8] = lvb;         pa.dst[8] = qkvb + 2*DIM;  pa.n[8] = DIM;
        pa.src[9] = lqb + DIM;   pa.dst[9] = qkvb + 3*DIM;  pa.n[9] = DIM;
        pa.src[10]= lkb + DIM;   pa.dst[10]= qkvb + 4*DIM;  pa.n[10]= DIM;
        pa.src[11]= lvb + DIM;   pa.dst[11]= qkvb + 5*DIM;  pa.n[11]= DIM;
        packf_kernel<<<dim3(64, 12), 256>>>(pa);
    }

    const dim3 gQKV(3*DIM/128, TOKENS/128);   // 24 x 32
    const dim3 gBig(DIM/128, TOKENS/128);     // 8 x 32
    const dim3 gSm (DIM/64, 1);               // 16 x 1
    const dim3 gSm3(3*DIM/64, 1);             // 48 x 1
    const dim3 gAtt(SEQ/64, HEADS, BATCH);    // 32 x 16 x 2
    const dim3 gCAtt(HEADS, BATCH);

    // ---- local layer 0 ----
    gemm_plain<<<gQKV, 256, GEMM_H_SMEM>>>(xh, hqkv, DIM, qkvb, nullptr, 1, 0, nullptr, qkvh, TOKENS, 3*DIM, DIM, 0, nullptr);
    flash_attn_h<<<gAtt, 128>>>(qkvh, 3*DIM, atth);
    gemm_plain<<<gBig, 256, GEMM_H_SMEM>>>(atth, hlo, DIM, lob, x, 1, DIM, h1, h1h, TOKENS, DIM, DIM, 0, nullptr);

    // ---- local layer 1 ----
    gemm_plain<<<gQKV, 256, GEMM_H_SMEM>>>(h1h, hqkv + 3*DD, DIM, qkvb + 3*DIM, nullptr, 1, 0, nullptr, qkvh, TOKENS, 3*DIM, DIM, 0, nullptr);
    flash_attn_h<<<gAtt, 128>>>(qkvh, 3*DIM, atth);
    gemm_plain<<<gBig, 256, GEMM_H_SMEM>>>(atth, hlo + DD, DIM, lob + DIM, h1, 1, DIM, h2, h2h, TOKENS, DIM, DIM, 0, nullptr);
    // h2 = x_local (fp32) / h2h (fp16)

    // ---- cluster path ----
    cluster_mean<<<NCLUST, 256>>>(h2, reps);
    cluster_diff<<<BATCH, DIM>>>(reps, mlpin);
    gemm_sm<<<gSm, 256, GEMM_SMEM_SM>>>(mlpin, m1w, DIM, m1b, nullptr, 1, t1, NCLUST, DIM, DIM, 1);
    gemm_sm<<<gSm, 256, GEMM_SMEM_SM>>>(t1, m2w, DIM, m2b, reps, 1, mix, NCLUST, DIM, DIM, 0);
    gemm_sm<<<gSm3, 256, GEMM_SMEM_SM>>>(mix, gqkvw, DIM, gqkvb, nullptr, 1, rqkv, NCLUST, 3*DIM, DIM, 0);
    cluster_attn<<<gCAtt, 32>>>(rqkv, ratt);
    gemm_sm<<<gSm, 256, GEMM_SMEM_SM>>>(ratt, gow, DIM, gob, nullptr, 1, rnew, NCLUST, DIM, DIM, 0);

    // gproj = reps_new @ W1b^T (second half of g1w columns, ldb = 2*DIM)
    gemm_sm<<<gSm, 256, GEMM_SMEM_SM>>>(rnew, g1w + DIM, 2*DIM, nullptr, nullptr, 1, gproj, NCLUST, DIM, DIM, 0);

    // hidden = gelu(x_local @ W1a^T + g1b + broadcast(gproj))
    gemm_plain<<<gBig, 256, GEMM_H_SMEM>>>(h2h, hg1, 2*DIM, g1b, gproj, 64, DIM, nullptr, hidh, TOKENS, DIM, DIM, 1, nullptr);
    // out = x_local + sigmoid(hidden @ g2w^T + g2b) * (broadcast(rnew) - x_local)   [fused, dedicated kernel]
    gemm_merge<<<gBig, 256, GEMM_H_SMEM>>>(hidh, hg2, DIM, g2b, rnew, 64, DIM, out, nullptr, TOKENS, DIM, DIM, 3, h2);
}